// round 13
// baseline (speedup 1.0000x reference)
#include <cuda_runtime.h>
#include <cuda_bf16.h>
#include <mma.h>

using namespace nvcuda;

#define NN   32768
#define DD   128
#define BB   64
#define NPGC 512
#define EE   524288
#define KCL  5
#define H2D  256
#define CBN  512

typedef __nv_bfloat16 bf16;

// ---------------- scratch (device globals; no runtime allocation) ----------------
__device__ float g_h[NN*DD];
__device__ float g_res[BB*DD];
__device__ float g_cfnum[BB*KCL*DD];
__device__ float g_ssum[BB*KCL];
__device__ int   g_off[NN+1], g_srcl[EE];
__device__ bf16  g_w1hi[3*DD*H2D], g_w1lo[3*DD*H2D];
__device__ bf16  g_w2hi[3*H2D*DD], g_w2lo[3*H2D*DD];
__device__ bf16  g_pwhi[DD*128],   g_pwlo[DD*128];   // partitioner W1 padded 50->128
__device__ float g_pb1[128];

__device__ __forceinline__ void bsplit(float v, bf16& hi, bf16& lo) {
    hi = __float2bfloat16(v);
    lo = __float2bfloat16(v - __bfloat162float(hi));
}

__device__ __forceinline__ void cpa16(void* dst, const void* src) {
    unsigned sa = (unsigned)__cvta_generic_to_shared(dst);
    asm volatile("cp.async.cg.shared.global [%0], [%1], 16;\n" :: "r"(sa), "l"(src));
}
#define CPA_COMMIT() asm volatile("cp.async.commit_group;\n" ::: "memory")
#define CPA_WAIT0()  asm volatile("cp.async.wait_group 0;\n" ::: "memory")

// ---------------- setup: per-graph CSR (blocks 0..63) + prep/embed/zero (blocks 64+) ----------------
__global__ void setup_kernel(const int* __restrict__ ei,
                             const int* __restrict__ x, const float* __restrict__ emb,
                             const float* __restrict__ gW1, const float* __restrict__ gW2,
                             const float* __restrict__ pW1, const float* __restrict__ pb1) {
    int t = threadIdx.x;
    if (blockIdx.x < 64) {
        __shared__ int cnt[512];
        __shared__ int offs[512];
        int g = blockIdx.x;
        cnt[t] = 0;
        if (t < 128) g_res[g*128 + t] = 0.0f;
        __syncthreads();
        int ebase = g*8192;
        int nbase = g*512;
        #pragma unroll
        for (int i = 0; i < 16; i++) {
            int e = ebase + t + i*512;
            int d = ei[EE + e] - nbase;            // local dst (edges stay in-graph)
            atomicAdd(&cnt[d], 1);
        }
        __syncthreads();
        offs[t] = cnt[t];
        __syncthreads();
        for (int off = 1; off < 512; off <<= 1) {
            int v = (t >= off) ? offs[t-off] : 0;
            __syncthreads();
            offs[t] += v;
            __syncthreads();
        }
        int excl = offs[t] - cnt[t];
        g_off[nbase + t] = ebase + excl;
        if (g == BB-1 && t == 511) g_off[NN] = EE;
        cnt[t] = excl;                              // reuse as scatter cursor
        __syncthreads();
        #pragma unroll
        for (int i = 0; i < 16; i++) {
            int e = ebase + t + i*512;
            int d = ei[EE + e] - nbase;
            int p = atomicAdd(&cnt[d], 1);
            g_srcl[ebase + p] = ei[e];
        }
        return;
    }
    const int tot = NN*DD + 3*DD*H2D + 3*H2D*DD + DD*128 + 128 + BB*KCL*DD + BB*KCL;
    int nb = gridDim.x - 64;
    for (int i0 = (blockIdx.x - 64)*512 + t; i0 < tot; i0 += nb*512) {
        int i = i0;
        if (i < NN*DD) { g_h[i] = emb[x[i >> 7]*DD + (i & 127)]; continue; }
        i -= NN*DD;
        if (i < 3*DD*H2D) { bsplit(gW1[i], g_w1hi[i], g_w1lo[i]); continue; }
        i -= 3*DD*H2D;
        if (i < 3*H2D*DD) { bsplit(gW2[i], g_w2hi[i], g_w2lo[i]); continue; }
        i -= 3*H2D*DD;
        if (i < DD*128) {
            int rw = i >> 7, cl = i & 127;
            float v = (cl < 50) ? pW1[rw*50 + cl] : 0.0f;
            bsplit(v, g_pwhi[i], g_pwlo[i]);
            continue;
        }
        i -= DD*128;
        if (i < 128) { g_pb1[i] = (i < 50) ? pb1[i] : 0.0f; continue; }
        i -= 128;
        if (i < BB*KCL*DD) { g_cfnum[i] = 0.0f; continue; }
        i -= BB*KCL*DD;
        g_ssum[i] = 0.0f;
    }
}

// ---------------- fused GIN layer, M=32 tile, 256 threads, occ-4; direct frag epilogues ----------------
#define ZLD  136
#define WLD  264
#define W2LD 136
#define GIN_SMEM 53376

__global__ __launch_bounds__(256, 4)
void ginlayer(const bf16* __restrict__ W1h, const bf16* __restrict__ W1l,
              const bf16* __restrict__ W2h, const bf16* __restrict__ W2l,
              const float* __restrict__ b1, const float* __restrict__ b2,
              const float* __restrict__ gamma, const float* __restrict__ beta,
              const bf16* __restrict__ Ph, const bf16* __restrict__ Pl,
              const float* __restrict__ pbias, const float* __restrict__ pW2,
              const float* __restrict__ pb2, int last)
{
    extern __shared__ __align__(16) char smem[];
    bf16*  sZh   = (bf16*)smem;
    bf16*  sZl   = sZh + 32*ZLD;                 // 4352 elems
    bf16*  wbase = (bf16*)(smem + 17408);        // W1 ping-pong, buf = 8448 elems
    bf16*  sHh   = (bf16*)smem;                  // 32x264
    bf16*  sHl   = sHh + 32*WLD;                 // 8448 elems
    bf16*  w2base= (bf16*)(smem + 33792);        // W2 ping-pong, buf = 4352 elems
    bf16*  sPh   = (bf16*)(smem + 17408);
    bf16*  sPl   = sPh + 32*W2LD;                // 4352 elems
    float* scrFp = (float*)(smem + 34816);
    float* w2s   = (float*)(smem + 51712);
    float* sScf  = (float*)(smem + 52736);       // 160 floats: S for 32 local nodes

    int t = threadIdx.x, w = t >> 5, lane = t & 31;
    int m0 = blockIdx.x*32;
    int lr = lane >> 2, lc = (lane & 3)*2;       // fragment layout coords

    // ---- prefetch W1 chunk 0 (16 K-rows, overlaps gather) ----
    {
        #pragma unroll
        for (int i = 0; i < 4; i++) {
            int idx = t + i*256;                 // 0..1023: hi 512 uint4, lo 512
            int m = idx >> 9, j = idx & 511;
            int r = j >> 5, p = j & 31;
            const bf16* src = (m ? W1l : W1h) + (size_t)r*256 + p*8;
            bf16* dst = wbase + m*(16*WLD) + r*WLD + p*8;
            cpa16(dst, src);
        }
        CPA_COMMIT();
    }

    // ---- Phase A: gather z (4 nodes per warp) ----
    {
        const float4* __restrict__ h4 = (const float4*)g_h;
        #pragma unroll
        for (int i = 0; i < 4; i++) {
            int r = w*4 + i;
            int node = m0 + r;
            float4 a = h4[(size_t)node*32 + lane];
            int e0 = g_off[node], e1 = g_off[node+1];
            int j = e0;
            for (; j + 4 <= e1; j += 4) {
                int s0 = g_srcl[j+0], s1 = g_srcl[j+1], s2 = g_srcl[j+2], s3 = g_srcl[j+3];
                float4 v0 = h4[(size_t)s0*32 + lane];
                float4 v1 = h4[(size_t)s1*32 + lane];
                float4 v2 = h4[(size_t)s2*32 + lane];
                float4 v3 = h4[(size_t)s3*32 + lane];
                a.x += (v0.x + v1.x) + (v2.x + v3.x);
                a.y += (v0.y + v1.y) + (v2.y + v3.y);
                a.z += (v0.z + v1.z) + (v2.z + v3.z);
                a.w += (v0.w + v1.w) + (v2.w + v3.w);
            }
            for (; j < e1; j++) {
                int s = g_srcl[j];
                float4 v = h4[(size_t)s*32 + lane];
                a.x += v.x; a.y += v.y; a.z += v.z; a.w += v.w;
            }
            __nv_bfloat162* ph = (__nv_bfloat162*)(sZh + r*ZLD);
            __nv_bfloat162* pl = (__nv_bfloat162*)(sZl + r*ZLD);
            bf16 h0,l0,h1,l1;
            bsplit(a.x, h0, l0); bsplit(a.y, h1, l1);
            ph[lane*2]   = __halves2bfloat162(h0, h1);
            pl[lane*2]   = __halves2bfloat162(l0, l1);
            bsplit(a.z, h0, l0); bsplit(a.w, h1, l1);
            ph[lane*2+1] = __halves2bfloat162(h0, h1);
            pl[lane*2+1] = __halves2bfloat162(l0, l1);
        }
    }
    CPA_WAIT0();
    __syncthreads();

    // ---- Phase B: gemm1  hidden[32x256] = z[32x128] @ W1[128x256], 8 chunks of 16 ----
    {
        wmma::fragment<wmma::accumulator,16,16,16,float> acc1[2][2];
        #pragma unroll
        for (int i = 0; i < 2; i++)
            #pragma unroll
            for (int j = 0; j < 2; j++)
                wmma::fill_fragment(acc1[i][j], 0.0f);

        #pragma unroll
        for (int c = 0; c < 8; c++) {
            const bf16* curH = wbase + (c&1)*8448;
            const bf16* curL = curH + 16*WLD;
            if (c < 7) {
                bf16* nb = wbase + ((c+1)&1)*8448;
                #pragma unroll
                for (int i = 0; i < 4; i++) {
                    int idx = t + i*256;
                    int m = idx >> 9, j = idx & 511;
                    int r = j >> 5, p = j & 31;
                    const bf16* src = (m ? W1l : W1h) + (size_t)((c+1)*16 + r)*256 + p*8;
                    bf16* dst = nb + m*(16*WLD) + r*WLD + p*8;
                    cpa16(dst, src);
                }
                CPA_COMMIT();
            }
            {
                int ko = c*16;
                wmma::fragment<wmma::matrix_a,16,16,16,bf16,wmma::row_major> ah[2], al[2];
                #pragma unroll
                for (int i = 0; i < 2; i++) {
                    wmma::load_matrix_sync(ah[i], sZh + (i*16)*ZLD + ko, ZLD);
                    wmma::load_matrix_sync(al[i], sZl + (i*16)*ZLD + ko, ZLD);
                }
                wmma::fragment<wmma::matrix_b,16,16,16,bf16,wmma::row_major> bh[2], bl[2];
                #pragma unroll
                for (int j = 0; j < 2; j++) {
                    wmma::load_matrix_sync(bh[j], curH + w*32 + j*16, WLD);
                    wmma::load_matrix_sync(bl[j], curL + w*32 + j*16, WLD);
                }
                #pragma unroll
                for (int i = 0; i < 2; i++)
                    #pragma unroll
                    for (int j = 0; j < 2; j++) {
                        wmma::mma_sync(acc1[i][j], ah[i], bh[j], acc1[i][j]);
                        wmma::mma_sync(acc1[i][j], ah[i], bl[j], acc1[i][j]);
                        wmma::mma_sync(acc1[i][j], al[i], bh[j], acc1[i][j]);
                    }
            }
            if (c < 7) CPA_WAIT0();
            __syncthreads();
        }

        // ---- prefetch W2 chunk 0 (overlaps Phase C epilogue; w2base region now free) ----
        {
            #pragma unroll
            for (int i = 0; i < 2; i++) {
                int idx = t + i*256;             // 0..511: hi 256 uint4, lo 256
                int m = idx >> 8, j = idx & 255;
                int r = j >> 4, p = j & 15;
                const bf16* src = (m ? W2l : W2h) + (size_t)r*128 + p*8;
                bf16* dst = w2base + m*(16*W2LD) + r*W2LD + p*8;
                cpa16(dst, src);
            }
            CPA_COMMIT();
        }

        // ---- Phase C: direct fragment epilogue (bias+relu+split) -> sHh/sHl ----
        // warp w owns rows 0..31 (i), cols w*32 + j*16 (j); frag elem e:
        //   row = i*16 + lr + 8*((e>>1)&1), col = base + lc + (e&1) + 8*(e>>2)
        #pragma unroll
        for (int i = 0; i < 2; i++)
            #pragma unroll
            for (int j = 0; j < 2; j++) {
                int cb = w*32 + j*16;
                #pragma unroll
                for (int e = 0; e < 8; e++) {
                    int row = i*16 + lr + (((e>>1)&1) << 3);
                    int col = cb + lc + (e&1) + ((e>>2) << 3);
                    float v = fmaxf(acc1[i][j].x[e] + __ldg(b1 + col), 0.0f);
                    bf16 hi, lo; bsplit(v, hi, lo);
                    sHh[row*WLD + col] = hi;
                    sHl[row*WLD + col] = lo;
                }
            }
    }
    CPA_WAIT0();
    __syncthreads();

    // ---- Phase D: gemm2  out[32x128] = hidden[32x256] @ W2[256x128], 16 chunks of 16 ----
    const float BNS = 0.99999500003749971f;    // 1/sqrt(1+1e-5)
    {
        int wm = w & 1, wn = w >> 1;             // 2 x 4 warps, warp tile 16x32
        wmma::fragment<wmma::accumulator,16,16,16,float> acc2[2];
        #pragma unroll
        for (int j = 0; j < 2; j++) wmma::fill_fragment(acc2[j], 0.0f);

        #pragma unroll
        for (int c2 = 0; c2 < 16; c2++) {
            const bf16* cH = w2base + (c2&1)*4352;
            const bf16* cL = cH + 16*W2LD;
            if (c2 < 15) {
                bf16* nb = w2base + ((c2+1)&1)*4352;
                #pragma unroll
                for (int i = 0; i < 2; i++) {
                    int idx = t + i*256;
                    int m = idx >> 8, j = idx & 255;
                    int r = j >> 4, p = j & 15;
                    const bf16* src = (m ? W2l : W2h) + (size_t)((c2+1)*16 + r)*128 + p*8;
                    bf16* dst = nb + m*(16*W2LD) + r*W2LD + p*8;
                    cpa16(dst, src);
                }
                CPA_COMMIT();
            }
            {
                int ko = c2*16;
                wmma::fragment<wmma::matrix_a,16,16,16,bf16,wmma::row_major> ah, al;
                wmma::load_matrix_sync(ah, sHh + (wm*16)*WLD + ko, WLD);
                wmma::load_matrix_sync(al, sHl + (wm*16)*WLD + ko, WLD);
                wmma::fragment<wmma::matrix_b,16,16,16,bf16,wmma::row_major> bh0, bh1, bl0, bl1;
                int nb2 = wn*32;
                wmma::load_matrix_sync(bh0, cH + nb2,      W2LD);
                wmma::load_matrix_sync(bh1, cH + nb2 + 16, W2LD);
                wmma::load_matrix_sync(bl0, cL + nb2,      W2LD);
                wmma::load_matrix_sync(bl1, cL + nb2 + 16, W2LD);
                wmma::mma_sync(acc2[0], ah, bh0, acc2[0]);
                wmma::mma_sync(acc2[1], ah, bh1, acc2[1]);
                wmma::mma_sync(acc2[0], ah, bl0, acc2[0]);
                wmma::mma_sync(acc2[1], ah, bl1, acc2[1]);
                wmma::mma_sync(acc2[0], al, bh0, acc2[0]);
                wmma::mma_sync(acc2[1], al, bh1, acc2[1]);
            }
            if (c2 < 15) CPA_WAIT0();
            __syncthreads();
        }

        // ---- Phase E: direct fragment epilogue (bias + BN [+relu]) -> g_h [+ split] ----
        #pragma unroll
        for (int j = 0; j < 2; j++) {
            int cb = wn*32 + j*16;
            #pragma unroll
            for (int e = 0; e < 8; e++) {
                int row = wm*16 + lr + (((e>>1)&1) << 3);
                int col = cb + lc + (e&1) + ((e>>2) << 3);
                float v = acc2[j].x[e] + __ldg(b2 + col);
                v = v*(BNS*__ldg(gamma + col)) + __ldg(beta + col);
                if (!last) v = fmaxf(v, 0.0f);
                g_h[(size_t)(m0 + row)*128 + col] = v;
                if (last) {
                    bf16 hi, lo; bsplit(v, hi, lo);
                    sZh[row*ZLD + col] = hi;
                    sZl[row*ZLD + col] = lo;
                }
            }
        }
    }

    if (!last) return;
    int g = m0 >> 9;

    // residue column sums from the act split
    __syncthreads();
    if (t < 128) {
        float rs = 0.0f;
        #pragma unroll 4
        for (int r = 0; r < 32; r++)
            rs += __bfloat162float(sZh[r*ZLD + t]) + __bfloat162float(sZl[r*ZLD + t]);
        atomicAdd(&g_res[g*128 + t], rs);
    }

    // ---- Phase F: fused partitioner  cl[32x128] = act[32x128] @ pW1[128x128], S -> smem ----
    {
        int wm = w & 1, wn = w >> 1;             // 2 x 4 warps, warp tile 16x32
        wmma::fragment<wmma::accumulator,16,16,16,float> acc3[2];
        #pragma unroll
        for (int i = 0; i < 2; i++) wmma::fill_fragment(acc3[i], 0.0f);

        #pragma unroll
        for (int c = 0; c < 4; c++) {
            __syncthreads();
            #pragma unroll
            for (int i = 0; i < 4; i++) {        // 1024 uint4: hi 512, lo 512
                int idx = t + i*256;
                int m = idx >> 9, j = idx & 511;
                int r = j >> 4, p = j & 15;
                const bf16* src = (m ? Pl : Ph) + (size_t)(c*32 + r)*128 + p*8;
                bf16* dst = (m ? sPl : sPh) + r*W2LD + p*8;
                *(uint4*)dst = *(const uint4*)src;
            }
            __syncthreads();
            #pragma unroll
            for (int kb = 0; kb < 2; kb++) {
                wmma::fragment<wmma::matrix_a,16,16,16,bf16,wmma::row_major> ah, al;
                wmma::load_matrix_sync(ah, sZh + (wm*16)*ZLD + c*32 + kb*16, ZLD);
                wmma::load_matrix_sync(al, sZl + (wm*16)*ZLD + c*32 + kb*16, ZLD);
                wmma::fragment<wmma::matrix_b,16,16,16,bf16,wmma::row_major> bh0, bh1, bl0, bl1;
                int nb2 = wn*32;
                wmma::load_matrix_sync(bh0, sPh + (kb*16)*W2LD + nb2,      W2LD);
                wmma::load_matrix_sync(bh1, sPh + (kb*16)*W2LD + nb2 + 16, W2LD);
                wmma::load_matrix_sync(bl0, sPl + (kb*16)*W2LD + nb2,      W2LD);
                wmma::load_matrix_sync(bl1, sPl + (kb*16)*W2LD + nb2 + 16, W2LD);
                wmma::mma_sync(acc3[0], ah, bh0, acc3[0]);
                wmma::mma_sync(acc3[1], ah, bh1, acc3[1]);
                wmma::mma_sync(acc3[0], ah, bl0, acc3[0]);
                wmma::mma_sync(acc3[1], ah, bl1, acc3[1]);
                wmma::mma_sync(acc3[0], al, bh0, acc3[0]);
                wmma::mma_sync(acc3[1], al, bh1, acc3[1]);
            }
        }
        __syncthreads();
        #pragma unroll
        for (int j = 0; j < 2; j++)
            wmma::store_matrix_sync(scrFp + ((w & 1)*16)*132 + (w >> 1)*32 + j*16, acc3[j],
                                    132, wmma::mem_row_major);
        if (t < 255) w2s[t] = (t < 250) ? pW2[t] : pb2[t - 250];
        __syncthreads();

        if (t < 32) {
            float cr[50];
            #pragma unroll
            for (int j = 0; j < 50; j++)
                cr[j] = fmaxf(scrFp[t*132 + j] + pbias[j], 0.0f);
            float l[5];
            #pragma unroll
            for (int k = 0; k < 5; k++) {
                float a = w2s[250 + k];
                #pragma unroll
                for (int j = 0; j < 50; j++) a += cr[j]*w2s[j*5 + k];
                l[k] = a;
            }
            float m = l[0];
            #pragma unroll
            for (int k = 1; k < 5; k++) m = fmaxf(m, l[k]);
            float e[5], s = 0.0f;
            #pragma unroll
            for (int k = 0; k < 5; k++) { e[k] = expf(l[k] - m); s += e[k]; }
            float inv = 1.0f/s;
            #pragma unroll
            for (int k = 0; k < 5; k++) sScf[t*5 + k] = e[k]*inv;
        }
    }
    __syncthreads();

    // ---- Phase G: cf partial accumulate (S^T h for own 32 nodes) ----
    {
        int c = t & 127, half = t >> 7;
        float acc[5] = {0,0,0,0,0};
        #pragma unroll 4
        for (int n = half*16; n < half*16 + 16; n++) {
            float hv = __bfloat162float(sZh[n*ZLD + c]) + __bfloat162float(sZl[n*ZLD + c]);
            #pragma unroll
            for (int k = 0; k < 5; k++) acc[k] += sScf[n*5 + k]*hv;
        }
        #pragma unroll
        for (int k = 0; k < 5; k++)
            atomicAdd(&g_cfnum[((size_t)g*5 + k)*128 + c], acc[k]);
        if (t < 5) {
            float s = 0.0f;
            #pragma unroll
            for (int n = 0; n < 32; n++) s += sScf[n*5 + t];
            atomicAdd(&g_ssum[g*5 + t], s);
        }
    }
}

// ---------------- finale: cf divide + VQ + attention/gate/classifier, one block per graph ----------------
__global__ void finale_kernel(const float* __restrict__ codebook,
                              const float* __restrict__ Wq, const float* __restrict__ Wk,
                              const float* __restrict__ Wv, const float* __restrict__ Wo,
                              const float* __restrict__ gW1, const float* __restrict__ gb1,
                              const float* __restrict__ gW2, const float* __restrict__ gb2,
                              const float* __restrict__ cW1, const float* __restrict__ cb1,
                              const float* __restrict__ cW2, const float* __restrict__ cb2,
                              const float* __restrict__ cW3, const float* __restrict__ cb3,
                              float* __restrict__ out)
{
    __shared__ __align__(16) float sh[2816];         // tail scratch
    __shared__ __align__(16) float cfv[5*128];
    __shared__ float zq5[5*128];
    __shared__ float wbest[5][4];
    __shared__ int   widx[5][4];
    __shared__ int   bidx[5];

    int g = blockIdx.x, t = threadIdx.x;             // 640 threads
    int k = t >> 7, c = t & 127;

    // ---- cf: divide ----
    cfv[k*128 + c] = g_cfnum[((size_t)g*5 + k)*128 + c] / (g_ssum[g*5 + k] + 1e-6f);
    __syncthreads();

    // ---- VQ: nearest codebook row per cluster (5 rows x 4 warps each) ----
    {
        int w4 = c >> 5, lane = c & 31;
        float4 fv = ((const float4*)(cfv + k*128))[lane];
        float best = 3.4e38f;
        int bi = 0;
        for (int rr = w4; rr < CBN; rr += 4) {
            const float4* cb4 = (const float4*)(codebook + (size_t)rr*128);
            float4 cv = cb4[lane];
            float dx = cv.x - fv.x, dy = cv.y - fv.y, dz = cv.z - fv.z, dw = cv.w - fv.w;
            float d = dx*dx + dy*dy + dz*dz + dw*dw;
            #pragma unroll
            for (int o = 16; o; o >>= 1) d += __shfl_xor_sync(0xffffffff, d, o);
            if (d < best) { best = d; bi = rr; }
        }
        if (lane == 0) { wbest[k][w4] = best; widx[k][w4] = bi; }
        __syncthreads();
        if (t < 5) {
            float bb = wbest[t][0]; int ii = widx[t][0];
            for (int j = 1; j < 4; j++)
                if (wbest[t][j] < bb || (wbest[t][j] == bb && widx[t][j] < ii)) { bb = wbest[t][j]; ii = widx[t][j]; }
            bidx[t] = ii;
        }
        __syncthreads();
        zq5[k*128 + c] = codebook[(size_t)bidx[k]*128 + c];
    }
    __syncthreads();

    // ---- tail: attention + gate + classifier ----
    float* r    = sh;            // 128
    float* qv   = sh + 128;      // 128
    float* kk   = sh + 256;      // 640
    float* vv   = sh + 896;      // 640
    float* sc   = sh + 1536;     // 20
    float* aw   = sh + 1568;     // 20
    float* attv = sh + 1600;     // 128
    float* attn = sh + 1728;     // 128
    float* g1   = sh + 1856;     // 64
    float* fus  = sh + 1920;     // 128
    float* z1   = sh + 2048;     // 512
    float* z2   = sh + 2560;     // 256

    if (t < 128) r[t] = g_res[g*128 + t]*(1.0f/NPGC);
    __syncthreads();

    if (t < 128) {
        float a = 0.0f;
        for (int k2 = 0; k2 < 128; k2++) a += r[k2]*Wq[k2*128 + t];
        qv[t] = a;
        float a5[5] = {0,0,0,0,0};
        for (int k2 = 0; k2 < 128; k2++) {
            float wv2 = Wk[k2*128 + t];
            #pragma unroll
            for (int j = 0; j < 5; j++) a5[j] += zq5[j*128 + k2]*wv2;
        }
        #pragma unroll
        for (int j = 0; j < 5; j++) kk[j*128 + t] = a5[j];
        float b5[5] = {0,0,0,0,0};
        for (int k2 = 0; k2 < 128; k2++) {
            float wv2 = Wv[k2*128 + t];
            #pragma unroll
            for (int j = 0; j < 5; j++) b5[j] += zq5[j*128 + k2]*wv2;
        }
        #pragma unroll
        for (int j = 0; j < 5; j++) vv[j*128 + t] = b5[j];
    }
    __syncthreads();

    if (t < 20) {
        int hh = t/5, j = t%5;
        float s = 0.0f;
        for (int d2 = 0; d2 < 32; d2++) s += qv[hh*32 + d2]*kk[j*128 + hh*32 + d2];
        sc[t] = s*0.17677669529663687f;              // 1/sqrt(32)
    }
    __syncthreads();
    if (t < 4) {
        float m = -1e30f;
        #pragma unroll
        for (int j = 0; j < 5; j++) m = fmaxf(m, sc[t*5 + j]);
        float e[5], s = 0.0f;
        #pragma unroll
        for (int j = 0; j < 5; j++) { e[j] = expf(sc[t*5 + j] - m); s += e[j]; }
        float inv = 1.0f/s;
        #pragma unroll
        for (int j = 0; j < 5; j++) aw[t*5 + j] = e[j]*inv;
    }
    __syncthreads();
    if (t < 128) {
        int hh = t >> 5;
        float a = 0.0f;
        #pragma unroll
        for (int j = 0; j < 5; j++) a += aw[hh*5 + j]*vv[j*128 + t];
        attv[t] = a;
    }
    __syncthreads();
    if (t < 128) {
        float a = 0.0f;
        for (int k2 = 0; k2 < 128; k2++) a += attv[k2]*Wo[k2*128 + t];
        attn[t] = a;
    }
    __syncthreads();
    if (t < 64) {
        float a = gb1[t];
        for (int k2 = 0; k2 < 128; k2++) a += r[k2]*gW1[k2*64 + t];
        for (int k2 = 0; k2 < 128; k2++) a += attn[k2]*gW1[(128 + k2)*64 + t];
        g1[t] = fmaxf(a, 0.0f);
    }
    __syncthreads();
    if (t < 128) {
        float a = gb2[t];
        for (int k2 = 0; k2 < 64; k2++) a += g1[k2]*gW2[k2*128 + t];
        float gg = 1.0f/(1.0f + expf(-a));
        fus[t] = gg*r[t] + (1.0f - gg)*attn[t];
    }
    __syncthreads();
    if (t < 512) {
        float a = cb1[t];
        for (int k2 = 0; k2 < 128; k2++) a += fus[k2]*cW1[k2*512 + t];
        z1[t] = fmaxf(a, 0.0f);
    }
    __syncthreads();
    if (t < 256) {
        float a = cb2[t];
        for (int k2 = 0; k2 < 512; k2++) a += z1[k2]*cW2[k2*256 + t];
        z2[t] = fmaxf(a, 0.0f);
    }
    __syncthreads();
    if (t < 2) {
        float a = cb3[t];
        for (int k2 = 0; k2 < 256; k2++) a += z2[k2]*cW3[k2*2 + t];
        out[g*2 + t] = a;
    }
}

// ---------------- host launch ----------------
extern "C" void kernel_launch(void* const* d_in, const int* in_sizes, int n_in,
                              void* d_out, int out_size) {
    (void)in_sizes; (void)n_in; (void)out_size;
    const int*   x     = (const int*)d_in[0];
    const int*   ei    = (const int*)d_in[1];
    const float* emb   = (const float*)d_in[3];
    const float* gW1   = (const float*)d_in[4];
    const float* gb1v  = (const float*)d_in[5];
    const float* gW2   = (const float*)d_in[6];
    const float* gb2v  = (const float*)d_in[7];
    const float* bng   = (const float*)d_in[8];
    const float* bnb   = (const float*)d_in[9];
    const float* pW1   = (const float*)d_in[10];
    const float* pb1   = (const float*)d_in[11];
    const float* pW2   = (const float*)d_in[12];
    const float* pb2   = (const float*)d_in[13];
    const float* Wq    = (const float*)d_in[14];
    const float* Wk    = (const float*)d_in[15];
    const float* Wv    = (const float*)d_in[16];
    const float* Wo    = (const float*)d_in[17];
    const float* gateW1= (const float*)d_in[18];
    const float* gateb1= (const float*)d_in[19];
    const float* gateW2= (const float*)d_in[20];
    const float* gateb2= (const float*)d_in[21];
    const float* cbk   = (const float*)d_in[22];
    const float* cW1   = (const float*)d_in[23];
    const float* cb1   = (const float*)d_in[24];
    const float* cW2   = (const float*)d_in[25];
    const float* cb2   = (const float*)d_in[26];
    const float* cW3   = (const float*)d_in[27];
    const float* cb3   = (const float*)d_in[28];
    float* out = (float*)d_out;

    bf16 *w1hi, *w1lo, *w2hi, *w2lo, *pwhi, *pwlo;
    float *ppb1;
    cudaGetSymbolAddress((void**)&w1hi, g_w1hi);
    cudaGetSymbolAddress((void**)&w1lo, g_w1lo);
    cudaGetSymbolAddress((void**)&w2hi, g_w2hi);
    cudaGetSymbolAddress((void**)&w2lo, g_w2lo);
    cudaGetSymbolAddress((void**)&pwhi, g_pwhi);
    cudaGetSymbolAddress((void**)&pwlo, g_pwlo);
    cudaGetSymbolAddress((void**)&ppb1, g_pb1);

    cudaFuncSetAttribute(ginlayer, cudaFuncAttributeMaxDynamicSharedMemorySize, GIN_SMEM);

    setup_kernel<<<64 + 1024, 512>>>(ei, x, emb, gW1, gW2, pW1, pb1);

    for (int l = 0; l < 3; l++) {
        ginlayer<<<NN/32, 256, GIN_SMEM>>>(
            w1hi + (size_t)l*DD*H2D, w1lo + (size_t)l*DD*H2D,
            w2hi + (size_t)l*H2D*DD, w2lo + (size_t)l*H2D*DD,
            gb1v + l*H2D, gb2v + l*DD, bng + l*DD, bnb + l*DD,
            pwhi, pwlo, ppb1, pW2, pb2,
            (l == 2) ? 1 : 0);
    }

    finale_kernel<<<BB, 640>>>(cbk, Wq, Wk, Wv, Wo, gateW1, gateb1, gateW2, gateb2,
                               cW1, cb1, cW2, cb2, cW3, cb3, out);
}

// round 14
// speedup vs baseline: 1.0889x; 1.0889x over previous
#include <cuda_runtime.h>
#include <cuda_bf16.h>
#include <mma.h>

using namespace nvcuda;

#define NN   32768
#define DD   128
#define BB   64
#define NPGC 512
#define EE   524288
#define KCL  5
#define H2D  256
#define CBN  512

typedef __nv_bfloat16 bf16;

// ---------------- scratch (device globals; no runtime allocation) ----------------
__device__ float g_h[NN*DD];
__device__ float g_res[BB*DD];
__device__ float g_cfnum[BB*KCL*DD];
__device__ float g_ssum[BB*KCL];
__device__ int   g_off[NN+1], g_srcl[EE];
__device__ bf16  g_w1hi[3*DD*H2D], g_w1lo[3*DD*H2D];
__device__ bf16  g_w2hi[3*H2D*DD], g_w2lo[3*H2D*DD];
__device__ bf16  g_pwhi[DD*128],   g_pwlo[DD*128];   // partitioner W1 padded 50->128
__device__ float g_pb1[128];

__device__ __forceinline__ void bsplit(float v, bf16& hi, bf16& lo) {
    hi = __float2bfloat16(v);
    lo = __float2bfloat16(v - __bfloat162float(hi));
}

__device__ __forceinline__ void cpa16(void* dst, const void* src) {
    unsigned sa = (unsigned)__cvta_generic_to_shared(dst);
    asm volatile("cp.async.cg.shared.global [%0], [%1], 16;\n" :: "r"(sa), "l"(src));
}
#define CPA_COMMIT() asm volatile("cp.async.commit_group;\n" ::: "memory")
#define CPA_WAIT0()  asm volatile("cp.async.wait_group 0;\n" ::: "memory")

// ---------------- setup: per-graph CSR (blocks 0..63) + prep/embed/zero (blocks 64+) ----------------
__global__ void setup_kernel(const int* __restrict__ ei,
                             const int* __restrict__ x, const float* __restrict__ emb,
                             const float* __restrict__ gW1, const float* __restrict__ gW2,
                             const float* __restrict__ pW1, const float* __restrict__ pb1) {
    int t = threadIdx.x;
    if (blockIdx.x < 64) {
        __shared__ int cnt[512];
        __shared__ int offs[512];
        int g = blockIdx.x;
        cnt[t] = 0;
        if (t < 128) g_res[g*128 + t] = 0.0f;
        __syncthreads();
        int ebase = g*8192;
        int nbase = g*512;
        #pragma unroll
        for (int i = 0; i < 16; i++) {
            int e = ebase + t + i*512;
            int d = ei[EE + e] - nbase;            // local dst (edges stay in-graph)
            atomicAdd(&cnt[d], 1);
        }
        __syncthreads();
        offs[t] = cnt[t];
        __syncthreads();
        for (int off = 1; off < 512; off <<= 1) {
            int v = (t >= off) ? offs[t-off] : 0;
            __syncthreads();
            offs[t] += v;
            __syncthreads();
        }
        int excl = offs[t] - cnt[t];
        g_off[nbase + t] = ebase + excl;
        if (g == BB-1 && t == 511) g_off[NN] = EE;
        cnt[t] = excl;                              // reuse as scatter cursor
        __syncthreads();
        #pragma unroll
        for (int i = 0; i < 16; i++) {
            int e = ebase + t + i*512;
            int d = ei[EE + e] - nbase;
            int p = atomicAdd(&cnt[d], 1);
            g_srcl[ebase + p] = ei[e];
        }
        return;
    }
    const int tot = NN*DD + 3*DD*H2D + 3*H2D*DD + DD*128 + 128 + BB*KCL*DD + BB*KCL;
    int nb = gridDim.x - 64;
    for (int i0 = (blockIdx.x - 64)*512 + t; i0 < tot; i0 += nb*512) {
        int i = i0;
        if (i < NN*DD) { g_h[i] = emb[x[i >> 7]*DD + (i & 127)]; continue; }
        i -= NN*DD;
        if (i < 3*DD*H2D) { bsplit(gW1[i], g_w1hi[i], g_w1lo[i]); continue; }
        i -= 3*DD*H2D;
        if (i < 3*H2D*DD) { bsplit(gW2[i], g_w2hi[i], g_w2lo[i]); continue; }
        i -= 3*H2D*DD;
        if (i < DD*128) {
            int rw = i >> 7, cl = i & 127;
            float v = (cl < 50) ? pW1[rw*50 + cl] : 0.0f;
            bsplit(v, g_pwhi[i], g_pwlo[i]);
            continue;
        }
        i -= DD*128;
        if (i < 128) { g_pb1[i] = (i < 50) ? pb1[i] : 0.0f; continue; }
        i -= 128;
        if (i < BB*KCL*DD) { g_cfnum[i] = 0.0f; continue; }
        i -= BB*KCL*DD;
        g_ssum[i] = 0.0f;
    }
}

// ---------------- fused GIN layer, M=32 tile, 256 threads, occ-4 (R12 form) ----------------
#define ZLD  136
#define WLD  264
#define W2LD 136
#define GIN_SMEM 53376

__global__ __launch_bounds__(256, 4)
void ginlayer(const bf16* __restrict__ W1h, const bf16* __restrict__ W1l,
              const bf16* __restrict__ W2h, const bf16* __restrict__ W2l,
              const float* __restrict__ b1, const float* __restrict__ b2,
              const float* __restrict__ gamma, const float* __restrict__ beta,
              const bf16* __restrict__ Ph, const bf16* __restrict__ Pl,
              const float* __restrict__ pbias, const float* __restrict__ pW2,
              const float* __restrict__ pb2, int last)
{
    extern __shared__ __align__(16) char smem[];
    bf16*  sZh   = (bf16*)smem;
    bf16*  sZl   = sZh + 32*ZLD;                 // 4352 elems
    bf16*  wbase = (bf16*)(smem + 17408);        // W1 ping-pong, buf = 8448 elems
    bf16*  sHh   = (bf16*)smem;                  // 32x264
    bf16*  sHl   = sHh + 32*WLD;                 // 8448 elems
    float* scrF  = (float*)(smem + 33792);
    bf16*  w2base= (bf16*)(smem + 33792);        // W2 ping-pong, buf = 4352 elems
    bf16*  sPh   = (bf16*)(smem + 17408);
    bf16*  sPl   = sPh + 32*W2LD;                // 4352 elems
    float* scrFp = (float*)(smem + 34816);
    float* w2s   = (float*)(smem + 51712);
    float* sScf  = (float*)(smem + 52736);       // 160 floats: S for 32 local nodes

    int t = threadIdx.x, w = t >> 5, lane = t & 31;
    int m0 = blockIdx.x*32;

    // ---- prefetch W1 chunk 0 (16 K-rows, overlaps gather) ----
    {
        #pragma unroll
        for (int i = 0; i < 4; i++) {
            int idx = t + i*256;                 // 0..1023: hi 512 uint4, lo 512
            int m = idx >> 9, j = idx & 511;
            int r = j >> 5, p = j & 31;
            const bf16* src = (m ? W1l : W1h) + (size_t)r*256 + p*8;
            bf16* dst = wbase + m*(16*WLD) + r*WLD + p*8;
            cpa16(dst, src);
        }
        CPA_COMMIT();
    }

    // ---- Phase A: gather z (4 nodes per warp) ----
    {
        const float4* __restrict__ h4 = (const float4*)g_h;
        #pragma unroll
        for (int i = 0; i < 4; i++) {
            int r = w*4 + i;
            int node = m0 + r;
            float4 a = h4[(size_t)node*32 + lane];
            int e0 = g_off[node], e1 = g_off[node+1];
            int j = e0;
            for (; j + 4 <= e1; j += 4) {
                int s0 = g_srcl[j+0], s1 = g_srcl[j+1], s2 = g_srcl[j+2], s3 = g_srcl[j+3];
                float4 v0 = h4[(size_t)s0*32 + lane];
                float4 v1 = h4[(size_t)s1*32 + lane];
                float4 v2 = h4[(size_t)s2*32 + lane];
                float4 v3 = h4[(size_t)s3*32 + lane];
                a.x += (v0.x + v1.x) + (v2.x + v3.x);
                a.y += (v0.y + v1.y) + (v2.y + v3.y);
                a.z += (v0.z + v1.z) + (v2.z + v3.z);
                a.w += (v0.w + v1.w) + (v2.w + v3.w);
            }
            for (; j < e1; j++) {
                int s = g_srcl[j];
                float4 v = h4[(size_t)s*32 + lane];
                a.x += v.x; a.y += v.y; a.z += v.z; a.w += v.w;
            }
            __nv_bfloat162* ph = (__nv_bfloat162*)(sZh + r*ZLD);
            __nv_bfloat162* pl = (__nv_bfloat162*)(sZl + r*ZLD);
            bf16 h0,l0,h1,l1;
            bsplit(a.x, h0, l0); bsplit(a.y, h1, l1);
            ph[lane*2]   = __halves2bfloat162(h0, h1);
            pl[lane*2]   = __halves2bfloat162(l0, l1);
            bsplit(a.z, h0, l0); bsplit(a.w, h1, l1);
            ph[lane*2+1] = __halves2bfloat162(h0, h1);
            pl[lane*2+1] = __halves2bfloat162(l0, l1);
        }
    }
    CPA_WAIT0();
    __syncthreads();

    // ---- Phase B: gemm1  hidden[32x256] = z[32x128] @ W1[128x256], 8 chunks of 16 ----
    {
        wmma::fragment<wmma::accumulator,16,16,16,float> acc1[2][2];
        #pragma unroll
        for (int i = 0; i < 2; i++)
            #pragma unroll
            for (int j = 0; j < 2; j++)
                wmma::fill_fragment(acc1[i][j], 0.0f);

        #pragma unroll
        for (int c = 0; c < 8; c++) {
            const bf16* curH = wbase + (c&1)*8448;
            const bf16* curL = curH + 16*WLD;
            if (c < 7) {
                bf16* nb = wbase + ((c+1)&1)*8448;
                #pragma unroll
                for (int i = 0; i < 4; i++) {
                    int idx = t + i*256;
                    int m = idx >> 9, j = idx & 511;
                    int r = j >> 5, p = j & 31;
                    const bf16* src = (m ? W1l : W1h) + (size_t)((c+1)*16 + r)*256 + p*8;
                    bf16* dst = nb + m*(16*WLD) + r*WLD + p*8;
                    cpa16(dst, src);
                }
                CPA_COMMIT();
            }
            {
                int ko = c*16;
                wmma::fragment<wmma::matrix_a,16,16,16,bf16,wmma::row_major> ah[2], al[2];
                #pragma unroll
                for (int i = 0; i < 2; i++) {
                    wmma::load_matrix_sync(ah[i], sZh + (i*16)*ZLD + ko, ZLD);
                    wmma::load_matrix_sync(al[i], sZl + (i*16)*ZLD + ko, ZLD);
                }
                wmma::fragment<wmma::matrix_b,16,16,16,bf16,wmma::row_major> bh[2], bl[2];
                #pragma unroll
                for (int j = 0; j < 2; j++) {
                    wmma::load_matrix_sync(bh[j], curH + w*32 + j*16, WLD);
                    wmma::load_matrix_sync(bl[j], curL + w*32 + j*16, WLD);
                }
                #pragma unroll
                for (int i = 0; i < 2; i++)
                    #pragma unroll
                    for (int j = 0; j < 2; j++) {
                        wmma::mma_sync(acc1[i][j], ah[i], bh[j], acc1[i][j]);
                        wmma::mma_sync(acc1[i][j], ah[i], bl[j], acc1[i][j]);
                        wmma::mma_sync(acc1[i][j], al[i], bh[j], acc1[i][j]);
                    }
            }
            if (c < 7) CPA_WAIT0();
            __syncthreads();
        }

        // ---- Phase C: hidden epilogue (bias+relu+split), 2 N-halves via scrF ----
        #pragma unroll
        for (int r = 0; r < 2; r++) {
            if (r) __syncthreads();
            if ((w >> 2) == r) {
                #pragma unroll
                for (int i = 0; i < 2; i++)
                    #pragma unroll
                    for (int j = 0; j < 2; j++)
                        wmma::store_matrix_sync(scrF + (i*16)*132 + (w & 3)*32 + j*16,
                                                acc1[i][j], 132, wmma::mem_row_major);
            }
            __syncthreads();
            #pragma unroll 4
            for (int it = 0; it < 16; it++) {
                int idx = t + it*256;
                int rr = idx >> 7, c = idx & 127;
                int C = r*128 + c;
                float v = fmaxf(scrF[rr*132 + c] + __ldg(b1 + C), 0.0f);
                bf16 hi, lo; bsplit(v, hi, lo);
                sHh[rr*WLD + C] = hi;
                sHl[rr*WLD + C] = lo;
            }
        }
    }
    __syncthreads();

    // ---- Phase D: gemm2  out[32x128] = hidden[32x256] @ W2[256x128], 16 chunks of 16 ----
    {
        int wm = w & 1, wn = w >> 1;             // 2 x 4 warps, warp tile 16x32
        wmma::fragment<wmma::accumulator,16,16,16,float> acc2[2];
        #pragma unroll
        for (int j = 0; j < 2; j++) wmma::fill_fragment(acc2[j], 0.0f);

        {
            #pragma unroll
            for (int i = 0; i < 2; i++) {
                int idx = t + i*256;             // 0..511: hi 256 uint4, lo 256
                int m = idx >> 8, j = idx & 255;
                int r = j >> 4, p = j & 15;
                const bf16* src = (m ? W2l : W2h) + (size_t)r*128 + p*8;
                bf16* dst = w2base + m*(16*W2LD) + r*W2LD + p*8;
                cpa16(dst, src);
            }
            CPA_COMMIT();
        }
        CPA_WAIT0();
        __syncthreads();

        #pragma unroll
        for (int c2 = 0; c2 < 16; c2++) {
            const bf16* cH = w2base + (c2&1)*4352;
            const bf16* cL = cH + 16*W2LD;
            if (c2 < 15) {
                bf16* nb = w2base + ((c2+1)&1)*4352;
                #pragma unroll
                for (int i = 0; i < 2; i++) {
                    int idx = t + i*256;
                    int m = idx >> 8, j = idx & 255;
                    int r = j >> 4, p = j & 15;
                    const bf16* src = (m ? W2l : W2h) + (size_t)((c2+1)*16 + r)*128 + p*8;
                    bf16* dst = nb + m*(16*W2LD) + r*W2LD + p*8;
                    cpa16(dst, src);
                }
                CPA_COMMIT();
            }
            {
                int ko = c2*16;
                wmma::fragment<wmma::matrix_a,16,16,16,bf16,wmma::row_major> ah, al;
                wmma::load_matrix_sync(ah, sHh + (wm*16)*WLD + ko, WLD);
                wmma::load_matrix_sync(al, sHl + (wm*16)*WLD + ko, WLD);
                wmma::fragment<wmma::matrix_b,16,16,16,bf16,wmma::row_major> bh0, bh1, bl0, bl1;
                int nb2 = wn*32;
                wmma::load_matrix_sync(bh0, cH + nb2,      W2LD);
                wmma::load_matrix_sync(bh1, cH + nb2 + 16, W2LD);
                wmma::load_matrix_sync(bl0, cL + nb2,      W2LD);
                wmma::load_matrix_sync(bl1, cL + nb2 + 16, W2LD);
                wmma::mma_sync(acc2[0], ah, bh0, acc2[0]);
                wmma::mma_sync(acc2[1], ah, bh1, acc2[1]);
                wmma::mma_sync(acc2[0], ah, bl0, acc2[0]);
                wmma::mma_sync(acc2[1], ah, bl1, acc2[1]);
                wmma::mma_sync(acc2[0], al, bh0, acc2[0]);
                wmma::mma_sync(acc2[1], al, bh1, acc2[1]);
            }
            if (c2 < 15) CPA_WAIT0();
            __syncthreads();
        }
        #pragma unroll
        for (int j = 0; j < 2; j++)
            wmma::store_matrix_sync(scrF + (wm*16)*132 + wn*32 + j*16, acc2[j],
                                    132, wmma::mem_row_major);
        __syncthreads();
    }

    // ---- Phase E: final epilogue (bias + BN [+relu]) -> g_h [+ act-split to smem, residue] ----
    const float BNS = 0.99999500003749971f;    // 1/sqrt(1+1e-5)
    {
        int ccol = t & 127;
        float rsum = 0.0f;
        #pragma unroll 4
        for (int it = 0; it < 16; it++) {
            int idx = t + it*256;
            int r = idx >> 7;                      // 0..31
            float v = scrF[r*132 + ccol] + __ldg(b2 + ccol);
            v = v*(BNS*__ldg(gamma + ccol)) + __ldg(beta + ccol);
            if (!last) v = fmaxf(v, 0.0f);
            size_t gi = (size_t)(m0 + r)*128 + ccol;
            g_h[gi] = v;
            if (last) {
                bf16 hi, lo; bsplit(v, hi, lo);
                sZh[r*ZLD + ccol] = hi;            // act split -> z region (hidden dead)
                sZl[r*ZLD + ccol] = lo;
                rsum += v;
            }
        }
        if (last)
            atomicAdd(&g_res[(m0 >> 9)*128 + ccol], rsum);
    }

    if (!last) return;
    int g = m0 >> 9;

    // ---- Phase F: fused partitioner  cl[32x128] = act[32x128] @ pW1[128x128], S -> smem ----
    {
        int wm = w & 1, wn = w >> 1;             // 2 x 4 warps, warp tile 16x32
        wmma::fragment<wmma::accumulator,16,16,16,float> acc3[2];
        #pragma unroll
        for (int i = 0; i < 2; i++) wmma::fill_fragment(acc3[i], 0.0f);

        #pragma unroll
        for (int c = 0; c < 4; c++) {
            __syncthreads();
            #pragma unroll
            for (int i = 0; i < 4; i++) {        // 1024 uint4: hi 512, lo 512
                int idx = t + i*256;
                int m = idx >> 9, j = idx & 511;
                int r = j >> 4, p = j & 15;
                const bf16* src = (m ? Pl : Ph) + (size_t)(c*32 + r)*128 + p*8;
                bf16* dst = (m ? sPl : sPh) + r*W2LD + p*8;
                *(uint4*)dst = *(const uint4*)src;
            }
            __syncthreads();
            #pragma unroll
            for (int kb = 0; kb < 2; kb++) {
                wmma::fragment<wmma::matrix_a,16,16,16,bf16,wmma::row_major> ah, al;
                wmma::load_matrix_sync(ah, sZh + (wm*16)*ZLD + c*32 + kb*16, ZLD);
                wmma::load_matrix_sync(al, sZl + (wm*16)*ZLD + c*32 + kb*16, ZLD);
                wmma::fragment<wmma::matrix_b,16,16,16,bf16,wmma::row_major> bh0, bh1, bl0, bl1;
                int nb2 = wn*32;
                wmma::load_matrix_sync(bh0, sPh + (kb*16)*W2LD + nb2,      W2LD);
                wmma::load_matrix_sync(bh1, sPh + (kb*16)*W2LD + nb2 + 16, W2LD);
                wmma::load_matrix_sync(bl0, sPl + (kb*16)*W2LD + nb2,      W2LD);
                wmma::load_matrix_sync(bl1, sPl + (kb*16)*W2LD + nb2 + 16, W2LD);
                wmma::mma_sync(acc3[0], ah, bh0, acc3[0]);
                wmma::mma_sync(acc3[1], ah, bh1, acc3[1]);
                wmma::mma_sync(acc3[0], ah, bl0, acc3[0]);
                wmma::mma_sync(acc3[1], ah, bl1, acc3[1]);
                wmma::mma_sync(acc3[0], al, bh0, acc3[0]);
                wmma::mma_sync(acc3[1], al, bh1, acc3[1]);
            }
        }
        __syncthreads();
        #pragma unroll
        for (int j = 0; j < 2; j++)
            wmma::store_matrix_sync(scrFp + ((w & 1)*16)*132 + (w >> 1)*32 + j*16, acc3[j],
                                    132, wmma::mem_row_major);
        if (t < 255) w2s[t] = (t < 250) ? pW2[t] : pb2[t - 250];
        __syncthreads();

        if (t < 32) {
            float cr[50];
            #pragma unroll
            for (int j = 0; j < 50; j++)
                cr[j] = fmaxf(scrFp[t*132 + j] + pbias[j], 0.0f);
            float l[5];
            #pragma unroll
            for (int k = 0; k < 5; k++) {
                float a = w2s[250 + k];
                #pragma unroll
                for (int j = 0; j < 50; j++) a += cr[j]*w2s[j*5 + k];
                l[k] = a;
            }
            float m = l[0];
            #pragma unroll
            for (int k = 1; k < 5; k++) m = fmaxf(m, l[k]);
            float e[5], s = 0.0f;
            #pragma unroll
            for (int k = 0; k < 5; k++) { e[k] = expf(l[k] - m); s += e[k]; }
            float inv = 1.0f/s;
            #pragma unroll
            for (int k = 0; k < 5; k++) sScf[t*5 + k] = e[k]*inv;
        }
    }
    __syncthreads();

    // ---- Phase G: cf partial accumulate (S^T h for own 32 nodes) ----
    {
        int c = t & 127, half = t >> 7;
        float acc[5] = {0,0,0,0,0};
        #pragma unroll 4
        for (int n = half*16; n < half*16 + 16; n++) {
            float hv = __bfloat162float(sZh[n*ZLD + c]) + __bfloat162float(sZl[n*ZLD + c]);
            #pragma unroll
            for (int k = 0; k < 5; k++) acc[k] += sScf[n*5 + k]*hv;
        }
        #pragma unroll
        for (int k = 0; k < 5; k++)
            atomicAdd(&g_cfnum[((size_t)g*5 + k)*128 + c], acc[k]);
        if (t < 5) {
            float s = 0.0f;
            #pragma unroll
            for (int n = 0; n < 32; n++) s += sScf[n*5 + t];
            atomicAdd(&g_ssum[g*5 + t], s);
        }
    }
}

// ---------------- finale: cf divide + VQ + attention/gate/classifier, one block per graph ----------------
__global__ void finale_kernel(const float* __restrict__ codebook,
                              const float* __restrict__ Wq, const float* __restrict__ Wk,
                              const float* __restrict__ Wv, const float* __restrict__ Wo,
                              const float* __restrict__ gW1, const float* __restrict__ gb1,
                              const float* __restrict__ gW2, const float* __restrict__ gb2,
                              const float* __restrict__ cW1, const float* __restrict__ cb1,
                              const float* __restrict__ cW2, const float* __restrict__ cb2,
                              const float* __restrict__ cW3, const float* __restrict__ cb3,
                              float* __restrict__ out)
{
    __shared__ __align__(16) float sh[2816];         // tail scratch
    __shared__ __align__(16) float cfv[5*128];
    __shared__ float zq5[5*128];
    __shared__ float wbest[5][4];
    __shared__ int   widx[5][4];
    __shared__ int   bidx[5];

    int g = blockIdx.x, t = threadIdx.x;             // 640 threads
    int k = t >> 7, c = t & 127;

    // ---- cf: divide ----
    cfv[k*128 + c] = g_cfnum[((size_t)g*5 + k)*128 + c] / (g_ssum[g*5 + k] + 1e-6f);
    __syncthreads();

    // ---- VQ: nearest codebook row per cluster (5 rows x 4 warps each) ----
    {
        int w4 = c >> 5, lane = c & 31;
        float4 fv = ((const float4*)(cfv + k*128))[lane];
        float best = 3.4e38f;
        int bi = 0;
        for (int rr = w4; rr < CBN; rr += 4) {
            const float4* cb4 = (const float4*)(codebook + (size_t)rr*128);
            float4 cv = cb4[lane];
            float dx = cv.x - fv.x, dy = cv.y - fv.y, dz = cv.z - fv.z, dw = cv.w - fv.w;
            float d = dx*dx + dy*dy + dz*dz + dw*dw;
            #pragma unroll
            for (int o = 16; o; o >>= 1) d += __shfl_xor_sync(0xffffffff, d, o);
            if (d < best) { best = d; bi = rr; }
        }
        if (lane == 0) { wbest[k][w4] = best; widx[k][w4] = bi; }
        __syncthreads();
        if (t < 5) {
            float bb = wbest[t][0]; int ii = widx[t][0];
            for (int j = 1; j < 4; j++)
                if (wbest[t][j] < bb || (wbest[t][j] == bb && widx[t][j] < ii)) { bb = wbest[t][j]; ii = widx[t][j]; }
            bidx[t] = ii;
        }
        __syncthreads();
        zq5[k*128 + c] = codebook[(size_t)bidx[k]*128 + c];
    }
    __syncthreads();

    // ---- tail: attention + gate + classifier ----
    float* r    = sh;            // 128
    float* qv   = sh + 128;      // 128
    float* kk   = sh + 256;      // 640
    float* vv   = sh + 896;      // 640
    float* sc   = sh + 1536;     // 20
    float* aw   = sh + 1568;     // 20
    float* attv = sh + 1600;     // 128
    float* attn = sh + 1728;     // 128
    float* g1   = sh + 1856;     // 64
    float* fus  = sh + 1920;     // 128
    float* z1   = sh + 2048;     // 512
    float* z2   = sh + 2560;     // 256

    if (t < 128) r[t] = g_res[g*128 + t]*(1.0f/NPGC);
    __syncthreads();

    // q projection (128 threads) + K/V projections spread across all 640 threads
    if (t < 128) {
        float a = 0.0f;
        for (int k2 = 0; k2 < 128; k2++) a += r[k2]*Wq[k2*128 + t];
        qv[t] = a;
    }
    {
        // kk[t]: cluster j = t>>7, output dim c = t&127
        float a = 0.0f;
        const float* zrow = zq5 + k*128;
        for (int k2 = 0; k2 < 128; k2++) a += zrow[k2]*Wk[k2*128 + c];
        kk[t] = a;
        float b = 0.0f;
        for (int k2 = 0; k2 < 128; k2++) b += zrow[k2]*Wv[k2*128 + c];
        vv[t] = b;
    }
    __syncthreads();

    if (t < 20) {
        int hh = t/5, j = t%5;
        float s = 0.0f;
        for (int d2 = 0; d2 < 32; d2++) s += qv[hh*32 + d2]*kk[j*128 + hh*32 + d2];
        sc[t] = s*0.17677669529663687f;              // 1/sqrt(32)
    }
    __syncthreads();
    if (t < 4) {
        float m = -1e30f;
        #pragma unroll
        for (int j = 0; j < 5; j++) m = fmaxf(m, sc[t*5 + j]);
        float e[5], s = 0.0f;
        #pragma unroll
        for (int j = 0; j < 5; j++) { e[j] = expf(sc[t*5 + j] - m); s += e[j]; }
        float inv = 1.0f/s;
        #pragma unroll
        for (int j = 0; j < 5; j++) aw[t*5 + j] = e[j]*inv;
    }
    __syncthreads();
    if (t < 128) {
        int hh = t >> 5;
        float a = 0.0f;
        #pragma unroll
        for (int j = 0; j < 5; j++) a += aw[hh*5 + j]*vv[j*128 + t];
        attv[t] = a;
    }
    __syncthreads();
    if (t < 128) {
        float a = 0.0f;
        for (int k2 = 0; k2 < 128; k2++) a += attv[k2]*Wo[k2*128 + t];
        attn[t] = a;
    }
    __syncthreads();
    if (t < 64) {
        float a = gb1[t];
        for (int k2 = 0; k2 < 128; k2++) a += r[k2]*gW1[k2*64 + t];
        for (int k2 = 0; k2 < 128; k2++) a += attn[k2]*gW1[(128 + k2)*64 + t];
        g1[t] = fmaxf(a, 0.0f);
    }
    __syncthreads();
    if (t < 128) {
        float a = gb2[t];
        for (int k2 = 0; k2 < 64; k2++) a += g1[k2]*gW2[k2*128 + t];
        float gg = 1.0f/(1.0f + expf(-a));
        fus[t] = gg*r[t] + (1.0f - gg)*attn[t];
    }
    __syncthreads();
    if (t < 512) {
        float a = cb1[t];
        for (int k2 = 0; k2 < 128; k2++) a += fus[k2]*cW1[k2*512 + t];
        z1[t] = fmaxf(a, 0.0f);
    }
    __syncthreads();
    if (t < 256) {
        float a = cb2[t];
        for (int k2 = 0; k2 < 512; k2++) a += z1[k2]*cW2[k2*256 + t];
        z2[t] = fmaxf(a, 0.0f);
    }
    __syncthreads();
    if (t < 2) {
        float a = cb3[t];
        for (int k2 = 0; k2 < 256; k2++) a += z2[k2]*cW3[k2*2 + t];
        out[g*2 + t] = a;
    }
}

// ---------------- host launch ----------------
extern "C" void kernel_launch(void* const* d_in, const int* in_sizes, int n_in,
                              void* d_out, int out_size) {
    (void)in_sizes; (void)n_in; (void)out_size;
    const int*   x     = (const int*)d_in[0];
    const int*   ei    = (const int*)d_in[1];
    const float* emb   = (const float*)d_in[3];
    const float* gW1   = (const float*)d_in[4];
    const float* gb1v  = (const float*)d_in[5];
    const float* gW2   = (const float*)d_in[6];
    const float* gb2v  = (const float*)d_in[7];
    const float* bng   = (const float*)d_in[8];
    const float* bnb   = (const float*)d_in[9];
    const float* pW1   = (const float*)d_in[10];
    const float* pb1   = (const float*)d_in[11];
    const float* pW2   = (const float*)d_in[12];
    const float* pb2   = (const float*)d_in[13];
    const float* Wq    = (const float*)d_in[14];
    const float* Wk    = (const float*)d_in[15];
    const float* Wv    = (const float*)d_in[16];
    const float* Wo    = (const float*)d_in[17];
    const float* gateW1= (const float*)d_in[18];
    const float* gateb1= (const float*)d_in[19];
    const float* gateW2= (const float*)d_in[20];
    const float* gateb2= (const float*)d_in[21];
    const float* cbk   = (const float*)d_in[22];
    const float* cW1   = (const float*)d_in[23];
    const float* cb1   = (const float*)d_in[24];
    const float* cW2   = (const float*)d_in[25];
    const float* cb2   = (const float*)d_in[26];
    const float* cW3   = (const float*)d_in[27];
    const float* cb3   = (const float*)d_in[28];
    float* out = (float*)d_out;

    bf16 *w1hi, *w1lo, *w2hi, *w2lo, *pwhi, *pwlo;
    float *ppb1;
    cudaGetSymbolAddress((void**)&w1hi, g_w1hi);
    cudaGetSymbolAddress((void**)&w1lo, g_w1lo);
    cudaGetSymbolAddress((void**)&w2hi, g_w2hi);
    cudaGetSymbolAddress((void**)&w2lo, g_w2lo);
    cudaGetSymbolAddress((void**)&pwhi, g_pwhi);
    cudaGetSymbolAddress((void**)&pwlo, g_pwlo);
    cudaGetSymbolAddress((void**)&ppb1, g_pb1);

    cudaFuncSetAttribute(ginlayer, cudaFuncAttributeMaxDynamicSharedMemorySize, GIN_SMEM);

    setup_kernel<<<64 + 1024, 512>>>(ei, x, emb, gW1, gW2, pW1, pb1);

    for (int l = 0; l < 3; l++) {
        ginlayer<<<NN/32, 256, GIN_SMEM>>>(
            w1hi + (size_t)l*DD*H2D, w1lo + (size_t)l*DD*H2D,
            w2hi + (size_t)l*H2D*DD, w2lo + (size_t)l*H2D*DD,
            gb1v + l*H2D, gb2v + l*DD, bng + l*DD, bnb + l*DD,
            pwhi, pwlo, ppb1, pW2, pb2,
            (l == 2) ? 1 : 0);
    }

    finale_kernel<<<BB, 640>>>(cbk, Wq, Wk, Wv, Wo, gateW1, gateb1, gateW2, gateb2,
                               cW1, cb1, cW2, cb2, cW3, cb3, out);
}

// round 15
// speedup vs baseline: 1.1382x; 1.0453x over previous
#include <cuda_runtime.h>
#include <cuda_bf16.h>
#include <mma.h>

using namespace nvcuda;

#define NN   32768
#define DD   128
#define BB   64
#define NPGC 512
#define EE   524288
#define KCL  5
#define H2D  256
#define CBN  512

typedef __nv_bfloat16 bf16;

// ---------------- scratch (device globals; no runtime allocation) ----------------
__device__ float g_h[NN*DD];
__device__ float g_res[BB*DD];
__device__ float g_cfnum[BB*KCL*DD];
__device__ float g_ssum[BB*KCL];
__device__ int   g_done[2*BB];
__device__ int   g_off[NN+1], g_srcl[EE];
__device__ bf16  g_w1hi[3*DD*H2D], g_w1lo[3*DD*H2D];
__device__ bf16  g_w2hi[3*H2D*DD], g_w2lo[3*H2D*DD];
__device__ bf16  g_pwhi[DD*128],   g_pwlo[DD*128];   // partitioner W1 padded 50->128
__device__ float g_pb1[128];

__device__ __forceinline__ void bsplit(float v, bf16& hi, bf16& lo) {
    hi = __float2bfloat16(v);
    lo = __float2bfloat16(v - __bfloat162float(hi));
}

__device__ __forceinline__ void cpa16(void* dst, const void* src) {
    unsigned sa = (unsigned)__cvta_generic_to_shared(dst);
    asm volatile("cp.async.cg.shared.global [%0], [%1], 16;\n" :: "r"(sa), "l"(src));
}
#define CPA_COMMIT() asm volatile("cp.async.commit_group;\n" ::: "memory")
#define CPA_WAIT0()  asm volatile("cp.async.wait_group 0;\n" ::: "memory")

// ---------------- setup: per-graph CSR (blocks 0..63) + prep/embed/zero (blocks 64+) ----------------
__global__ void setup_kernel(const int* __restrict__ ei,
                             const int* __restrict__ x, const float* __restrict__ emb,
                             const float* __restrict__ gW1, const float* __restrict__ gW2,
                             const float* __restrict__ pW1, const float* __restrict__ pb1) {
    int t = threadIdx.x;
    if (blockIdx.x < 64) {
        __shared__ int cnt[512];
        __shared__ int offs[512];
        int g = blockIdx.x;
        cnt[t] = 0;
        if (t < 128) g_res[g*128 + t] = 0.0f;
        if (t < 2) g_done[t*BB + g] = 0;
        __syncthreads();
        int ebase = g*8192;
        int nbase = g*512;
        #pragma unroll
        for (int i = 0; i < 16; i++) {
            int e = ebase + t + i*512;
            int d = ei[EE + e] - nbase;            // local dst (edges stay in-graph)
            atomicAdd(&cnt[d], 1);
        }
        __syncthreads();
        offs[t] = cnt[t];
        __syncthreads();
        for (int off = 1; off < 512; off <<= 1) {
            int v = (t >= off) ? offs[t-off] : 0;
            __syncthreads();
            offs[t] += v;
            __syncthreads();
        }
        int excl = offs[t] - cnt[t];
        g_off[nbase + t] = ebase + excl;
        if (g == BB-1 && t == 511) g_off[NN] = EE;
        cnt[t] = excl;                              // reuse as scatter cursor
        __syncthreads();
        #pragma unroll
        for (int i = 0; i < 16; i++) {
            int e = ebase + t + i*512;
            int d = ei[EE + e] - nbase;
            int p = atomicAdd(&cnt[d], 1);
            g_srcl[ebase + p] = ei[e];
        }
        return;
    }
    const int tot = NN*DD + 3*DD*H2D + 3*H2D*DD + DD*128 + 128 + BB*KCL*DD + BB*KCL;
    int nb = gridDim.x - 64;
    for (int i0 = (blockIdx.x - 64)*512 + t; i0 < tot; i0 += nb*512) {
        int i = i0;
        if (i < NN*DD) { g_h[i] = emb[x[i >> 7]*DD + (i & 127)]; continue; }
        i -= NN*DD;
        if (i < 3*DD*H2D) { bsplit(gW1[i], g_w1hi[i], g_w1lo[i]); continue; }
        i -= 3*DD*H2D;
        if (i < 3*H2D*DD) { bsplit(gW2[i], g_w2hi[i], g_w2lo[i]); continue; }
        i -= 3*H2D*DD;
        if (i < DD*128) {
            int rw = i >> 7, cl = i & 127;
            float v = (cl < 50) ? pW1[rw*50 + cl] : 0.0f;
            bsplit(v, g_pwhi[i], g_pwlo[i]);
            continue;
        }
        i -= DD*128;
        if (i < 128) { g_pb1[i] = (i < 50) ? pb1[i] : 0.0f; continue; }
        i -= 128;
        if (i < BB*KCL*DD) { g_cfnum[i] = 0.0f; continue; }
        i -= BB*KCL*DD;
        g_ssum[i] = 0.0f;
    }
}

// ---------------- fused 3-layer GIN, M=32 tile, 256 threads, occ-4, per-graph flow control ----------------
#define ZLD  136
#define WLD  264
#define W2LD 136
#define GIN_SMEM 53376

__global__ __launch_bounds__(256, 4)
void ginlayer(const bf16* __restrict__ W1hB, const bf16* __restrict__ W1lB,
              const bf16* __restrict__ W2hB, const bf16* __restrict__ W2lB,
              const float* __restrict__ b1B, const float* __restrict__ b2B,
              const float* __restrict__ gammaB, const float* __restrict__ betaB,
              const bf16* __restrict__ Ph, const bf16* __restrict__ Pl,
              const float* __restrict__ pbias, const float* __restrict__ pW2,
              const float* __restrict__ pb2)
{
    extern __shared__ __align__(16) char smem[];
    bf16*  sZh   = (bf16*)smem;
    bf16*  sZl   = sZh + 32*ZLD;                 // 4352 elems
    bf16*  wbase = (bf16*)(smem + 17408);        // W1 ping-pong, buf = 8448 elems
    bf16*  sHh   = (bf16*)smem;                  // 32x264
    bf16*  sHl   = sHh + 32*WLD;                 // 8448 elems
    float* scrF  = (float*)(smem + 33792);
    bf16*  w2base= (bf16*)(smem + 33792);        // W2 ping-pong, buf = 4352 elems
    bf16*  sPh   = (bf16*)(smem + 17408);
    bf16*  sPl   = sPh + 32*W2LD;                // 4352 elems
    float* scrFp = (float*)(smem + 34816);
    float* w2s   = (float*)(smem + 51712);
    float* sScf  = (float*)(smem + 52736);       // 160 floats: S for 32 local nodes

    int t = threadIdx.x, w = t >> 5, lane = t & 31;
    int l   = blockIdx.x >> 10;                  // layer 0..2
    int blk = blockIdx.x & 1023;
    int m0  = blk*32;
    int g   = blk >> 4;
    int last = (l == 2);

    const bf16*  W1h   = W1hB + (size_t)l*DD*H2D;
    const bf16*  W1l   = W1lB + (size_t)l*DD*H2D;
    const bf16*  W2h   = W2hB + (size_t)l*H2D*DD;
    const bf16*  W2l   = W2lB + (size_t)l*H2D*DD;
    const float* b1    = b1B + l*H2D;
    const float* b2    = b2B + l*DD;
    const float* gamma = gammaB + l*DD;
    const float* beta  = betaB + l*DD;

    // ---- prefetch W1 chunk 0 (16 K-rows, overlaps spin/gather) ----
    {
        #pragma unroll
        for (int i = 0; i < 4; i++) {
            int idx = t + i*256;                 // 0..1023: hi 512 uint4, lo 512
            int m = idx >> 9, j = idx & 511;
            int r = j >> 5, p = j & 31;
            const bf16* src = (m ? W1l : W1h) + (size_t)r*256 + p*8;
            bf16* dst = wbase + m*(16*WLD) + r*WLD + p*8;
            cpa16(dst, src);
        }
        CPA_COMMIT();
    }

    // ---- wait for previous layer of this graph (16 CTAs) ----
    if (l > 0) {
        if (t == 0) {
            while (atomicAdd(&g_done[(l-1)*BB + g], 0) < 16) { }
            __threadfence();
        }
        __syncthreads();
    }

    // ---- Phase A: gather z (4 nodes per warp) ----
    {
        const float4* __restrict__ h4 = (const float4*)g_h;
        #pragma unroll
        for (int i = 0; i < 4; i++) {
            int r = w*4 + i;
            int node = m0 + r;
            float4 a = h4[(size_t)node*32 + lane];
            int e0 = g_off[node], e1 = g_off[node+1];
            int j = e0;
            for (; j + 4 <= e1; j += 4) {
                int s0 = g_srcl[j+0], s1 = g_srcl[j+1], s2 = g_srcl[j+2], s3 = g_srcl[j+3];
                float4 v0 = h4[(size_t)s0*32 + lane];
                float4 v1 = h4[(size_t)s1*32 + lane];
                float4 v2 = h4[(size_t)s2*32 + lane];
                float4 v3 = h4[(size_t)s3*32 + lane];
                a.x += (v0.x + v1.x) + (v2.x + v3.x);
                a.y += (v0.y + v1.y) + (v2.y + v3.y);
                a.z += (v0.z + v1.z) + (v2.z + v3.z);
                a.w += (v0.w + v1.w) + (v2.w + v3.w);
            }
            for (; j < e1; j++) {
                int s = g_srcl[j];
                float4 v = h4[(size_t)s*32 + lane];
                a.x += v.x; a.y += v.y; a.z += v.z; a.w += v.w;
            }
            __nv_bfloat162* ph = (__nv_bfloat162*)(sZh + r*ZLD);
            __nv_bfloat162* pl = (__nv_bfloat162*)(sZl + r*ZLD);
            bf16 h0,l0,h1,l1;
            bsplit(a.x, h0, l0); bsplit(a.y, h1, l1);
            ph[lane*2]   = __halves2bfloat162(h0, h1);
            pl[lane*2]   = __halves2bfloat162(l0, l1);
            bsplit(a.z, h0, l0); bsplit(a.w, h1, l1);
            ph[lane*2+1] = __halves2bfloat162(h0, h1);
            pl[lane*2+1] = __halves2bfloat162(l0, l1);
        }
    }
    CPA_WAIT0();
    __syncthreads();

    // ---- Phase B: gemm1  hidden[32x256] = z[32x128] @ W1[128x256], 8 chunks of 16 ----
    {
        wmma::fragment<wmma::accumulator,16,16,16,float> acc1[2][2];
        #pragma unroll
        for (int i = 0; i < 2; i++)
            #pragma unroll
            for (int j = 0; j < 2; j++)
                wmma::fill_fragment(acc1[i][j], 0.0f);

        #pragma unroll
        for (int c = 0; c < 8; c++) {
            const bf16* curH = wbase + (c&1)*8448;
            const bf16* curL = curH + 16*WLD;
            if (c < 7) {
                bf16* nb = wbase + ((c+1)&1)*8448;
                #pragma unroll
                for (int i = 0; i < 4; i++) {
                    int idx = t + i*256;
                    int m = idx >> 9, j = idx & 511;
                    int r = j >> 5, p = j & 31;
                    const bf16* src = (m ? W1l : W1h) + (size_t)((c+1)*16 + r)*256 + p*8;
                    bf16* dst = nb + m*(16*WLD) + r*WLD + p*8;
                    cpa16(dst, src);
                }
                CPA_COMMIT();
            }
            {
                int ko = c*16;
                wmma::fragment<wmma::matrix_a,16,16,16,bf16,wmma::row_major> ah[2], al[2];
                #pragma unroll
                for (int i = 0; i < 2; i++) {
                    wmma::load_matrix_sync(ah[i], sZh + (i*16)*ZLD + ko, ZLD);
                    wmma::load_matrix_sync(al[i], sZl + (i*16)*ZLD + ko, ZLD);
                }
                wmma::fragment<wmma::matrix_b,16,16,16,bf16,wmma::row_major> bh[2], bl[2];
                #pragma unroll
                for (int j = 0; j < 2; j++) {
                    wmma::load_matrix_sync(bh[j], curH + w*32 + j*16, WLD);
                    wmma::load_matrix_sync(bl[j], curL + w*32 + j*16, WLD);
                }
                #pragma unroll
                for (int i = 0; i < 2; i++)
                    #pragma unroll
                    for (int j = 0; j < 2; j++) {
                        wmma::mma_sync(acc1[i][j], ah[i], bh[j], acc1[i][j]);
                        wmma::mma_sync(acc1[i][j], ah[i], bl[j], acc1[i][j]);
                        wmma::mma_sync(acc1[i][j], al[i], bh[j], acc1[i][j]);
                    }
            }
            if (c < 7) CPA_WAIT0();
            __syncthreads();
        }

        // ---- Phase C: hidden epilogue (bias+relu+split), 2 N-halves via scrF ----
        #pragma unroll
        for (int r = 0; r < 2; r++) {
            if (r) __syncthreads();
            if ((w >> 2) == r) {
                #pragma unroll
                for (int i = 0; i < 2; i++)
                    #pragma unroll
                    for (int j = 0; j < 2; j++)
                        wmma::store_matrix_sync(scrF + (i*16)*132 + (w & 3)*32 + j*16,
                                                acc1[i][j], 132, wmma::mem_row_major);
            }
            __syncthreads();
            #pragma unroll 4
            for (int it = 0; it < 16; it++) {
                int idx = t + it*256;
                int rr = idx >> 7, c = idx & 127;
                int C = r*128 + c;
                float v = fmaxf(scrF[rr*132 + c] + __ldg(b1 + C), 0.0f);
                bf16 hi, lo; bsplit(v, hi, lo);
                sHh[rr*WLD + C] = hi;
                sHl[rr*WLD + C] = lo;
            }
        }
    }
    __syncthreads();

    // ---- Phase D: gemm2  out[32x128] = hidden[32x256] @ W2[256x128], 16 chunks of 16 ----
    {
        int wm = w & 1, wn = w >> 1;             // 2 x 4 warps, warp tile 16x32
        wmma::fragment<wmma::accumulator,16,16,16,float> acc2[2];
        #pragma unroll
        for (int j = 0; j < 2; j++) wmma::fill_fragment(acc2[j], 0.0f);

        {
            #pragma unroll
            for (int i = 0; i < 2; i++) {
                int idx = t + i*256;             // 0..511: hi 256 uint4, lo 256
                int m = idx >> 8, j = idx & 255;
                int r = j >> 4, p = j & 15;
                const bf16* src = (m ? W2l : W2h) + (size_t)r*128 + p*8;
                bf16* dst = w2base + m*(16*W2LD) + r*W2LD + p*8;
                cpa16(dst, src);
            }
            CPA_COMMIT();
        }
        CPA_WAIT0();
        __syncthreads();

        #pragma unroll
        for (int c2 = 0; c2 < 16; c2++) {
            const bf16* cH = w2base + (c2&1)*4352;
            const bf16* cL = cH + 16*W2LD;
            if (c2 < 15) {
                bf16* nb = w2base + ((c2+1)&1)*4352;
                #pragma unroll
                for (int i = 0; i < 2; i++) {
                    int idx = t + i*256;
                    int m = idx >> 8, j = idx & 255;
                    int r = j >> 4, p = j & 15;
                    const bf16* src = (m ? W2l : W2h) + (size_t)((c2+1)*16 + r)*128 + p*8;
                    bf16* dst = nb + m*(16*W2LD) + r*W2LD + p*8;
                    cpa16(dst, src);
                }
                CPA_COMMIT();
            }
            {
                int ko = c2*16;
                wmma::fragment<wmma::matrix_a,16,16,16,bf16,wmma::row_major> ah, al;
                wmma::load_matrix_sync(ah, sHh + (wm*16)*WLD + ko, WLD);
                wmma::load_matrix_sync(al, sHl + (wm*16)*WLD + ko, WLD);
                wmma::fragment<wmma::matrix_b,16,16,16,bf16,wmma::row_major> bh0, bh1, bl0, bl1;
                int nb2 = wn*32;
                wmma::load_matrix_sync(bh0, cH + nb2,      W2LD);
                wmma::load_matrix_sync(bh1, cH + nb2 + 16, W2LD);
                wmma::load_matrix_sync(bl0, cL + nb2,      W2LD);
                wmma::load_matrix_sync(bl1, cL + nb2 + 16, W2LD);
                wmma::mma_sync(acc2[0], ah, bh0, acc2[0]);
                wmma::mma_sync(acc2[1], ah, bh1, acc2[1]);
                wmma::mma_sync(acc2[0], ah, bl0, acc2[0]);
                wmma::mma_sync(acc2[1], ah, bl1, acc2[1]);
                wmma::mma_sync(acc2[0], al, bh0, acc2[0]);
                wmma::mma_sync(acc2[1], al, bh1, acc2[1]);
            }
            if (c2 < 15) CPA_WAIT0();
            __syncthreads();
        }
        #pragma unroll
        for (int j = 0; j < 2; j++)
            wmma::store_matrix_sync(scrF + (wm*16)*132 + wn*32 + j*16, acc2[j],
                                    132, wmma::mem_row_major);
        __syncthreads();
    }

    // ---- Phase E: final epilogue (bias + BN [+relu]) -> g_h [+ act-split to smem, residue] ----
    const float BNS = 0.99999500003749971f;    // 1/sqrt(1+1e-5)
    {
        int ccol = t & 127;
        float rsum = 0.0f;
        #pragma unroll 4
        for (int it = 0; it < 16; it++) {
            int idx = t + it*256;
            int r = idx >> 7;                      // 0..31
            float v = scrF[r*132 + ccol] + __ldg(b2 + ccol);
            v = v*(BNS*__ldg(gamma + ccol)) + __ldg(beta + ccol);
            if (!last) v = fmaxf(v, 0.0f);
            size_t gi = (size_t)(m0 + r)*128 + ccol;
            g_h[gi] = v;
            if (last) {
                bf16 hi, lo; bsplit(v, hi, lo);
                sZh[r*ZLD + ccol] = hi;            // act split -> z region (hidden dead)
                sZl[r*ZLD + ccol] = lo;
                rsum += v;
            }
        }
        if (last)
            atomicAdd(&g_res[(m0 >> 9)*128 + ccol], rsum);
    }

    if (!last) {
        __threadfence();
        __syncthreads();
        if (t == 0) atomicAdd(&g_done[l*BB + g], 1);
        return;
    }

    // ---- Phase F: fused partitioner  cl[32x128] = act[32x128] @ pW1[128x128], S -> smem ----
    {
        int wm = w & 1, wn = w >> 1;             // 2 x 4 warps, warp tile 16x32
        wmma::fragment<wmma::accumulator,16,16,16,float> acc3[2];
        #pragma unroll
        for (int i = 0; i < 2; i++) wmma::fill_fragment(acc3[i], 0.0f);

        #pragma unroll
        for (int c = 0; c < 4; c++) {
            __syncthreads();
            #pragma unroll
            for (int i = 0; i < 4; i++) {        // 1024 uint4: hi 512, lo 512
                int idx = t + i*256;
                int m = idx >> 9, j = idx & 511;
                int r = j >> 4, p = j & 15;
                const bf16* src = (m ? Pl : Ph) + (size_t)(c*32 + r)*128 + p*8;
                bf16* dst = (m ? sPl : sPh) + r*W2LD + p*8;
                *(uint4*)dst = *(const uint4*)src;
            }
            __syncthreads();
            #pragma unroll
            for (int kb = 0; kb < 2; kb++) {
                wmma::fragment<wmma::matrix_a,16,16,16,bf16,wmma::row_major> ah, al;
                wmma::load_matrix_sync(ah, sZh + (wm*16)*ZLD + c*32 + kb*16, ZLD);
                wmma::load_matrix_sync(al, sZl + (wm*16)*ZLD + c*32 + kb*16, ZLD);
                wmma::fragment<wmma::matrix_b,16,16,16,bf16,wmma::row_major> bh0, bh1, bl0, bl1;
                int nb2 = wn*32;
                wmma::load_matrix_sync(bh0, sPh + (kb*16)*W2LD + nb2,      W2LD);
                wmma::load_matrix_sync(bh1, sPh + (kb*16)*W2LD + nb2 + 16, W2LD);
                wmma::load_matrix_sync(bl0, sPl + (kb*16)*W2LD + nb2,      W2LD);
                wmma::load_matrix_sync(bl1, sPl + (kb*16)*W2LD + nb2 + 16, W2LD);
                wmma::mma_sync(acc3[0], ah, bh0, acc3[0]);
                wmma::mma_sync(acc3[1], ah, bh1, acc3[1]);
                wmma::mma_sync(acc3[0], ah, bl0, acc3[0]);
                wmma::mma_sync(acc3[1], ah, bl1, acc3[1]);
                wmma::mma_sync(acc3[0], al, bh0, acc3[0]);
                wmma::mma_sync(acc3[1], al, bh1, acc3[1]);
            }
        }
        __syncthreads();
        #pragma unroll
        for (int j = 0; j < 2; j++)
            wmma::store_matrix_sync(scrFp + ((w & 1)*16)*132 + (w >> 1)*32 + j*16, acc3[j],
                                    132, wmma::mem_row_major);
        if (t < 255) w2s[t] = (t < 250) ? pW2[t] : pb2[t - 250];
        __syncthreads();

        if (t < 32) {
            float cr[50];
            #pragma unroll
            for (int j = 0; j < 50; j++)
                cr[j] = fmaxf(scrFp[t*132 + j] + pbias[j], 0.0f);
            float l2[5];
            #pragma unroll
            for (int k = 0; k < 5; k++) {
                float a = w2s[250 + k];
                #pragma unroll
                for (int j = 0; j < 50; j++) a += cr[j]*w2s[j*5 + k];
                l2[k] = a;
            }
            float m = l2[0];
            #pragma unroll
            for (int k = 1; k < 5; k++) m = fmaxf(m, l2[k]);
            float e[5], s = 0.0f;
            #pragma unroll
            for (int k = 0; k < 5; k++) { e[k] = expf(l2[k] - m); s += e[k]; }
            float inv = 1.0f/s;
            #pragma unroll
            for (int k = 0; k < 5; k++) sScf[t*5 + k] = e[k]*inv;
        }
    }
    __syncthreads();

    // ---- Phase G: cf partial accumulate (S^T h for own 32 nodes) ----
    {
        int c = t & 127, half = t >> 7;
        float acc[5] = {0,0,0,0,0};
        #pragma unroll 4
        for (int n = half*16; n < half*16 + 16; n++) {
            float hv = __bfloat162float(sZh[n*ZLD + c]) + __bfloat162float(sZl[n*ZLD + c]);
            #pragma unroll
            for (int k = 0; k < 5; k++) acc[k] += sScf[n*5 + k]*hv;
        }
        #pragma unroll
        for (int k = 0; k < 5; k++)
            atomicAdd(&g_cfnum[((size_t)g*5 + k)*128 + c], acc[k]);
        if (t < 5) {
            float s = 0.0f;
            #pragma unroll
            for (int n = 0; n < 32; n++) s += sScf[n*5 + t];
            atomicAdd(&g_ssum[g*5 + t], s);
        }
    }
}

// ---------------- finale: cf divide + VQ + attention/gate/classifier, one block per graph ----------------
__global__ void finale_kernel(const float* __restrict__ codebook,
                              const float* __restrict__ Wq, const float* __restrict__ Wk,
                              const float* __restrict__ Wv, const float* __restrict__ Wo,
                              const float* __restrict__ gW1, const float* __restrict__ gb1,
                              const float* __restrict__ gW2, const float* __restrict__ gb2,
                              const float* __restrict__ cW1, const float* __restrict__ cb1,
                              const float* __restrict__ cW2, const float* __restrict__ cb2,
                              const float* __restrict__ cW3, const float* __restrict__ cb3,
                              float* __restrict__ out)
{
    __shared__ __align__(16) float sh[2816];         // tail scratch
    __shared__ __align__(16) float cfv[5*128];
    __shared__ float zq5[5*128];
    __shared__ float wbest[5][4];
    __shared__ int   widx[5][4];
    __shared__ int   bidx[5];

    int g = blockIdx.x, t = threadIdx.x;             // 640 threads
    int k = t >> 7, c = t & 127;

    // ---- cf: divide ----
    cfv[k*128 + c] = g_cfnum[((size_t)g*5 + k)*128 + c] / (g_ssum[g*5 + k] + 1e-6f);
    __syncthreads();

    // ---- VQ: nearest codebook row per cluster (5 rows x 4 warps each) ----
    {
        int w4 = c >> 5, lane = c & 31;
        float4 fv = ((const float4*)(cfv + k*128))[lane];
        float best = 3.4e38f;
        int bi = 0;
        for (int rr = w4; rr < CBN; rr += 4) {
            const float4* cb4 = (const float4*)(codebook + (size_t)rr*128);
            float4 cv = cb4[lane];
            float dx = cv.x - fv.x, dy = cv.y - fv.y, dz = cv.z - fv.z, dw = cv.w - fv.w;
            float d = dx*dx + dy*dy + dz*dz + dw*dw;
            #pragma unroll
            for (int o = 16; o; o >>= 1) d += __shfl_xor_sync(0xffffffff, d, o);
            if (d < best) { best = d; bi = rr; }
        }
        if (lane == 0) { wbest[k][w4] = best; widx[k][w4] = bi; }
        __syncthreads();
        if (t < 5) {
            float bb = wbest[t][0]; int ii = widx[t][0];
            for (int j = 1; j < 4; j++)
                if (wbest[t][j] < bb || (wbest[t][j] == bb && widx[t][j] < ii)) { bb = wbest[t][j]; ii = widx[t][j]; }
            bidx[t] = ii;
        }
        __syncthreads();
        zq5[k*128 + c] = codebook[(size_t)bidx[k]*128 + c];
    }
    __syncthreads();

    // ---- tail: attention + gate + classifier ----
    float* r    = sh;            // 128
    float* qv   = sh + 128;      // 128
    float* kk   = sh + 256;      // 640
    float* vv   = sh + 896;      // 640
    float* sc   = sh + 1536;     // 20
    float* aw   = sh + 1568;     // 20
    float* attv = sh + 1600;     // 128
    float* attn = sh + 1728;     // 128
    float* g1   = sh + 1856;     // 64
    float* fus  = sh + 1920;     // 128
    float* z1   = sh + 2048;     // 512
    float* z2   = sh + 2560;     // 256

    if (t < 128) r[t] = g_res[g*128 + t]*(1.0f/NPGC);
    __syncthreads();

    if (t < 128) {
        float a = 0.0f;
        for (int k2 = 0; k2 < 128; k2++) a += r[k2]*Wq[k2*128 + t];
        qv[t] = a;
    }
    {
        float a = 0.0f;
        const float* zrow = zq5 + k*128;
        for (int k2 = 0; k2 < 128; k2++) a += zrow[k2]*Wk[k2*128 + c];
        kk[t] = a;
        float b = 0.0f;
        for (int k2 = 0; k2 < 128; k2++) b += zrow[k2]*Wv[k2*128 + c];
        vv[t] = b;
    }
    __syncthreads();

    if (t < 20) {
        int hh = t/5, j = t%5;
        float s = 0.0f;
        for (int d2 = 0; d2 < 32; d2++) s += qv[hh*32 + d2]*kk[j*128 + hh*32 + d2];
        sc[t] = s*0.17677669529663687f;              // 1/sqrt(32)
    }
    __syncthreads();
    if (t < 4) {
        float m = -1e30f;
        #pragma unroll
        for (int j = 0; j < 5; j++) m = fmaxf(m, sc[t*5 + j]);
        float e[5], s = 0.0f;
        #pragma unroll
        for (int j = 0; j < 5; j++) { e[j] = expf(sc[t*5 + j] - m); s += e[j]; }
        float inv = 1.0f/s;
        #pragma unroll
        for (int j = 0; j < 5; j++) aw[t*5 + j] = e[j]*inv;
    }
    __syncthreads();
    if (t < 128) {
        int hh = t >> 5;
        float a = 0.0f;
        #pragma unroll
        for (int j = 0; j < 5; j++) a += aw[hh*5 + j]*vv[j*128 + t];
        attv[t] = a;
    }
    __syncthreads();
    if (t < 128) {
        float a = 0.0f;
        for (int k2 = 0; k2 < 128; k2++) a += attv[k2]*Wo[k2*128 + t];
        attn[t] = a;
    }
    __syncthreads();
    if (t < 64) {
        float a = gb1[t];
        for (int k2 = 0; k2 < 128; k2++) a += r[k2]*gW1[k2*64 + t];
        for (int k2 = 0; k2 < 128; k2++) a += attn[k2]*gW1[(128 + k2)*64 + t];
        g1[t] = fmaxf(a, 0.0f);
    }
    __syncthreads();
    if (t < 128) {
        float a = gb2[t];
        for (int k2 = 0; k2 < 64; k2++) a += g1[k2]*gW2[k2*128 + t];
        float gg = 1.0f/(1.0f + expf(-a));
        fus[t] = gg*r[t] + (1.0f - gg)*attn[t];
    }
    __syncthreads();
    if (t < 512) {
        float a = cb1[t];
        for (int k2 = 0; k2 < 128; k2++) a += fus[k2]*cW1[k2*512 + t];
        z1[t] = fmaxf(a, 0.0f);
    }
    __syncthreads();
    if (t < 256) {
        float a = cb2[t];
        for (int k2 = 0; k2 < 512; k2++) a += z1[k2]*cW2[k2*256 + t];
        z2[t] = fmaxf(a, 0.0f);
    }
    __syncthreads();
    if (t < 2) {
        float a = cb3[t];
        for (int k2 = 0; k2 < 256; k2++) a += z2[k2]*cW3[k2*2 + t];
        out[g*2 + t] = a;
    }
}

// ---------------- host launch ----------------
extern "C" void kernel_launch(void* const* d_in, const int* in_sizes, int n_in,
                              void* d_out, int out_size) {
    (void)in_sizes; (void)n_in; (void)out_size;
    const int*   x     = (const int*)d_in[0];
    const int*   ei    = (const int*)d_in[1];
    const float* emb   = (const float*)d_in[3];
    const float* gW1   = (const float*)d_in[4];
    const float* gb1v  = (const float*)d_in[5];
    const float* gW2   = (const float*)d_in[6];
    const float* gb2v  = (const float*)d_in[7];
    const float* bng   = (const float*)d_in[8];
    const float* bnb   = (const float*)d_in[9];
    const float* pW1   = (const float*)d_in[10];
    const float* pb1   = (const float*)d_in[11];
    const float* pW2   = (const float*)d_in[12];
    const float* pb2   = (const float*)d_in[13];
    const float* Wq    = (const float*)d_in[14];
    const float* Wk    = (const float*)d_in[15];
    const float* Wv    = (const float*)d_in[16];
    const float* Wo    = (const float*)d_in[17];
    const float* gateW1= (const float*)d_in[18];
    const float* gateb1= (const float*)d_in[19];
    const float* gateW2= (const float*)d_in[20];
    const float* gateb2= (const float*)d_in[21];
    const float* cbk   = (const float*)d_in[22];
    const float* cW1   = (const float*)d_in[23];
    const float* cb1   = (const float*)d_in[24];
    const float* cW2   = (const float*)d_in[25];
    const float* cb2   = (const float*)d_in[26];
    const float* cW3   = (const float*)d_in[27];
    const float* cb3   = (const float*)d_in[28];
    float* out = (float*)d_out;

    bf16 *w1hi, *w1lo, *w2hi, *w2lo, *pwhi, *pwlo;
    float *ppb1;
    cudaGetSymbolAddress((void**)&w1hi, g_w1hi);
    cudaGetSymbolAddress((void**)&w1lo, g_w1lo);
    cudaGetSymbolAddress((void**)&w2hi, g_w2hi);
    cudaGetSymbolAddress((void**)&w2lo, g_w2lo);
    cudaGetSymbolAddress((void**)&pwhi, g_pwhi);
    cudaGetSymbolAddress((void**)&pwlo, g_pwlo);
    cudaGetSymbolAddress((void**)&ppb1, g_pb1);

    cudaFuncSetAttribute(ginlayer, cudaFuncAttributeMaxDynamicSharedMemorySize, GIN_SMEM);

    setup_kernel<<<64 + 1024, 512>>>(ei, x, emb, gW1, gW2, pW1, pb1);

    ginlayer<<<3*(NN/32), 256, GIN_SMEM>>>(
        w1hi, w1lo, w2hi, w2lo,
        gb1v, gb2v, bng, bnb,
        pwhi, pwlo, ppb1, pW2, pb2);

    finale_kernel<<<BB, 640>>>(cbk, Wq, Wk, Wv, Wo, gateW1, gateb1, gateW2, gateb2,
                               cW1, cb1, cW2, cb2, cW3, cb3, out);
}

// round 16
// speedup vs baseline: 1.1594x; 1.0186x over previous
#include <cuda_runtime.h>
#include <cuda_bf16.h>
#include <mma.h>

using namespace nvcuda;

#define NN   32768
#define DD   128
#define BB   64
#define NPGC 512
#define EE   524288
#define KCL  5
#define H2D  256
#define CBN  512

typedef __nv_bfloat16 bf16;

// ---------------- scratch (device globals; no runtime allocation) ----------------
__device__ float g_h[NN*DD];
__device__ float g_res[BB*DD];
__device__ float g_cfnum[BB*KCL*DD];
__device__ float g_ssum[BB*KCL];
__device__ int   g_done[2*BB];
__device__ int   g_off[NN+1], g_srcl[EE];
__device__ bf16  g_w1hi[3*DD*H2D], g_w1lo[3*DD*H2D];
__device__ bf16  g_w2hi[3*H2D*DD], g_w2lo[3*H2D*DD];
__device__ bf16  g_pwhi[DD*128],   g_pwlo[DD*128];   // partitioner W1 padded 50->128
__device__ float g_pb1[128];

__device__ __forceinline__ void bsplit(float v, bf16& hi, bf16& lo) {
    hi = __float2bfloat16(v);
    lo = __float2bfloat16(v - __bfloat162float(hi));
}

__device__ __forceinline__ void cpa16(void* dst, const void* src) {
    unsigned sa = (unsigned)__cvta_generic_to_shared(dst);
    asm volatile("cp.async.cg.shared.global [%0], [%1], 16;\n" :: "r"(sa), "l"(src));
}
#define CPA_COMMIT() asm volatile("cp.async.commit_group;\n" ::: "memory")
#define CPA_WAIT0()  asm volatile("cp.async.wait_group 0;\n" ::: "memory")

// ---------------- setup: per-graph CSR (blocks 0..63) + weight-split/zero (blocks 64+) ----------------
__global__ void setup_kernel(const int* __restrict__ ei,
                             const float* __restrict__ gW1, const float* __restrict__ gW2,
                             const float* __restrict__ pW1, const float* __restrict__ pb1) {
    int t = threadIdx.x;
    if (blockIdx.x < 64) {
        __shared__ int cnt[512];
        __shared__ int offs[512];
        int g = blockIdx.x;
        cnt[t] = 0;
        if (t < 128) g_res[g*128 + t] = 0.0f;
        if (t < 2) g_done[t*BB + g] = 0;
        __syncthreads();
        int ebase = g*8192;
        int nbase = g*512;
        #pragma unroll
        for (int i = 0; i < 16; i++) {
            int e = ebase + t + i*512;
            int d = ei[EE + e] - nbase;            // local dst (edges stay in-graph)
            atomicAdd(&cnt[d], 1);
        }
        __syncthreads();
        offs[t] = cnt[t];
        __syncthreads();
        for (int off = 1; off < 512; off <<= 1) {
            int v = (t >= off) ? offs[t-off] : 0;
            __syncthreads();
            offs[t] += v;
            __syncthreads();
        }
        int excl = offs[t] - cnt[t];
        g_off[nbase + t] = ebase + excl;
        if (g == BB-1 && t == 511) g_off[NN] = EE;
        cnt[t] = excl;                              // reuse as scatter cursor
        __syncthreads();
        #pragma unroll
        for (int i = 0; i < 16; i++) {
            int e = ebase + t + i*512;
            int d = ei[EE + e] - nbase;
            int p = atomicAdd(&cnt[d], 1);
            g_srcl[ebase + p] = ei[e];
        }
        return;
    }
    const int tot = 3*DD*H2D + 3*H2D*DD + DD*128 + 128 + BB*KCL*DD + BB*KCL;
    int nb = gridDim.x - 64;
    for (int i0 = (blockIdx.x - 64)*512 + t; i0 < tot; i0 += nb*512) {
        int i = i0;
        if (i < 3*DD*H2D) { bsplit(gW1[i], g_w1hi[i], g_w1lo[i]); continue; }
        i -= 3*DD*H2D;
        if (i < 3*H2D*DD) { bsplit(gW2[i], g_w2hi[i], g_w2lo[i]); continue; }
        i -= 3*H2D*DD;
        if (i < DD*128) {
            int rw = i >> 7, cl = i & 127;
            float v = (cl < 50) ? pW1[rw*50 + cl] : 0.0f;
            bsplit(v, g_pwhi[i], g_pwlo[i]);
            continue;
        }
        i -= DD*128;
        if (i < 128) { g_pb1[i] = (i < 50) ? pb1[i] : 0.0f; continue; }
        i -= 128;
        if (i < BB*KCL*DD) { g_cfnum[i] = 0.0f; continue; }
        i -= BB*KCL*DD;
        g_ssum[i] = 0.0f;
    }
}

// ---------------- fused 3-layer GIN, M=32 tile, 256 threads, occ-4, per-graph flow control ----------------
#define ZLD  136
#define WLD  264
#define W2LD 136
#define GIN_SMEM 53376

__global__ __launch_bounds__(256, 4)
void ginlayer(const bf16* __restrict__ W1hB, const bf16* __restrict__ W1lB,
              const bf16* __restrict__ W2hB, const bf16* __restrict__ W2lB,
              const float* __restrict__ b1B, const float* __restrict__ b2B,
              const float* __restrict__ gammaB, const float* __restrict__ betaB,
              const bf16* __restrict__ Ph, const bf16* __restrict__ Pl,
              const float* __restrict__ pbias, const float* __restrict__ pW2,
              const float* __restrict__ pb2,
              const int* __restrict__ xv, const float* __restrict__ embp)
{
    extern __shared__ __align__(16) char smem[];
    bf16*  sZh   = (bf16*)smem;
    bf16*  sZl   = sZh + 32*ZLD;                 // 4352 elems
    bf16*  wbase = (bf16*)(smem + 17408);        // W1 ping-pong, buf = 8448 elems
    bf16*  sHh   = (bf16*)smem;                  // 32x264
    bf16*  sHl   = sHh + 32*WLD;                 // 8448 elems
    float* scrF  = (float*)(smem + 33792);
    bf16*  w2base= (bf16*)(smem + 33792);        // W2 ping-pong, buf = 4352 elems
    bf16*  sPh   = (bf16*)(smem + 17408);
    bf16*  sPl   = sPh + 32*W2LD;                // 4352 elems
    float* scrFp = (float*)(smem + 34816);
    float* w2s   = (float*)(smem + 51712);
    float* sScf  = (float*)(smem + 52736);       // 160 floats: S for 32 local nodes

    int t = threadIdx.x, w = t >> 5, lane = t & 31;
    int l   = blockIdx.x >> 10;                  // layer 0..2
    int blk = blockIdx.x & 1023;
    int m0  = blk*32;
    int g   = blk >> 4;
    int last = (l == 2);

    const bf16*  W1h   = W1hB + (size_t)l*DD*H2D;
    const bf16*  W1l   = W1lB + (size_t)l*DD*H2D;
    const bf16*  W2h   = W2hB + (size_t)l*H2D*DD;
    const bf16*  W2l   = W2lB + (size_t)l*H2D*DD;
    const float* b1    = b1B + l*H2D;
    const float* b2    = b2B + l*DD;
    const float* gamma = gammaB + l*DD;
    const float* beta  = betaB + l*DD;

    // ---- prefetch W1 chunk 0 (16 K-rows, overlaps spin/gather) ----
    {
        #pragma unroll
        for (int i = 0; i < 4; i++) {
            int idx = t + i*256;                 // 0..1023: hi 512 uint4, lo 512
            int m = idx >> 9, j = idx & 511;
            int r = j >> 5, p = j & 31;
            const bf16* src = (m ? W1l : W1h) + (size_t)r*256 + p*8;
            bf16* dst = wbase + m*(16*WLD) + r*WLD + p*8;
            cpa16(dst, src);
        }
        CPA_COMMIT();
    }

    // ---- wait for previous layer of this graph (16 CTAs) ----
    if (l > 0) {
        if (t == 0) {
            while (atomicAdd(&g_done[(l-1)*BB + g], 0) < 16) { }
            __threadfence();
        }
        __syncthreads();
    }

    // ---- Phase A: gather z (4 nodes per warp); layer 0 computes emb on the fly ----
    if (l == 0) {
        const float4* __restrict__ e4 = (const float4*)embp;
        #pragma unroll
        for (int i = 0; i < 4; i++) {
            int r = w*4 + i;
            int node = m0 + r;
            float4 a = e4[(size_t)xv[node]*32 + lane];
            int e0 = g_off[node], e1 = g_off[node+1];
            int j = e0;
            for (; j + 4 <= e1; j += 4) {
                int s0 = g_srcl[j+0], s1 = g_srcl[j+1], s2 = g_srcl[j+2], s3 = g_srcl[j+3];
                int x0 = xv[s0], x1 = xv[s1], x2 = xv[s2], x3 = xv[s3];
                float4 v0 = e4[(size_t)x0*32 + lane];
                float4 v1 = e4[(size_t)x1*32 + lane];
                float4 v2 = e4[(size_t)x2*32 + lane];
                float4 v3 = e4[(size_t)x3*32 + lane];
                a.x += (v0.x + v1.x) + (v2.x + v3.x);
                a.y += (v0.y + v1.y) + (v2.y + v3.y);
                a.z += (v0.z + v1.z) + (v2.z + v3.z);
                a.w += (v0.w + v1.w) + (v2.w + v3.w);
            }
            for (; j < e1; j++) {
                float4 v = e4[(size_t)xv[g_srcl[j]]*32 + lane];
                a.x += v.x; a.y += v.y; a.z += v.z; a.w += v.w;
            }
            __nv_bfloat162* ph = (__nv_bfloat162*)(sZh + r*ZLD);
            __nv_bfloat162* pl = (__nv_bfloat162*)(sZl + r*ZLD);
            bf16 h0,l0,h1,l1;
            bsplit(a.x, h0, l0); bsplit(a.y, h1, l1);
            ph[lane*2]   = __halves2bfloat162(h0, h1);
            pl[lane*2]   = __halves2bfloat162(l0, l1);
            bsplit(a.z, h0, l0); bsplit(a.w, h1, l1);
            ph[lane*2+1] = __halves2bfloat162(h0, h1);
            pl[lane*2+1] = __halves2bfloat162(l0, l1);
        }
    } else {
        const float4* __restrict__ h4 = (const float4*)g_h;
        #pragma unroll
        for (int i = 0; i < 4; i++) {
            int r = w*4 + i;
            int node = m0 + r;
            float4 a = h4[(size_t)node*32 + lane];
            int e0 = g_off[node], e1 = g_off[node+1];
            int j = e0;
            for (; j + 4 <= e1; j += 4) {
                int s0 = g_srcl[j+0], s1 = g_srcl[j+1], s2 = g_srcl[j+2], s3 = g_srcl[j+3];
                float4 v0 = h4[(size_t)s0*32 + lane];
                float4 v1 = h4[(size_t)s1*32 + lane];
                float4 v2 = h4[(size_t)s2*32 + lane];
                float4 v3 = h4[(size_t)s3*32 + lane];
                a.x += (v0.x + v1.x) + (v2.x + v3.x);
                a.y += (v0.y + v1.y) + (v2.y + v3.y);
                a.z += (v0.z + v1.z) + (v2.z + v3.z);
                a.w += (v0.w + v1.w) + (v2.w + v3.w);
            }
            for (; j < e1; j++) {
                int s = g_srcl[j];
                float4 v = h4[(size_t)s*32 + lane];
                a.x += v.x; a.y += v.y; a.z += v.z; a.w += v.w;
            }
            __nv_bfloat162* ph = (__nv_bfloat162*)(sZh + r*ZLD);
            __nv_bfloat162* pl = (__nv_bfloat162*)(sZl + r*ZLD);
            bf16 h0,l0,h1,l1;
            bsplit(a.x, h0, l0); bsplit(a.y, h1, l1);
            ph[lane*2]   = __halves2bfloat162(h0, h1);
            pl[lane*2]   = __halves2bfloat162(l0, l1);
            bsplit(a.z, h0, l0); bsplit(a.w, h1, l1);
            ph[lane*2+1] = __halves2bfloat162(h0, h1);
            pl[lane*2+1] = __halves2bfloat162(l0, l1);
        }
    }
    CPA_WAIT0();
    __syncthreads();

    // ---- Phase B: gemm1  hidden[32x256] = z[32x128] @ W1[128x256], 8 chunks of 16 ----
    {
        wmma::fragment<wmma::accumulator,16,16,16,float> acc1[2][2];
        #pragma unroll
        for (int i = 0; i < 2; i++)
            #pragma unroll
            for (int j = 0; j < 2; j++)
                wmma::fill_fragment(acc1[i][j], 0.0f);

        #pragma unroll
        for (int c = 0; c < 8; c++) {
            const bf16* curH = wbase + (c&1)*8448;
            const bf16* curL = curH + 16*WLD;
            if (c < 7) {
                bf16* nb = wbase + ((c+1)&1)*8448;
                #pragma unroll
                for (int i = 0; i < 4; i++) {
                    int idx = t + i*256;
                    int m = idx >> 9, j = idx & 511;
                    int r = j >> 5, p = j & 31;
                    const bf16* src = (m ? W1l : W1h) + (size_t)((c+1)*16 + r)*256 + p*8;
                    bf16* dst = nb + m*(16*WLD) + r*WLD + p*8;
                    cpa16(dst, src);
                }
                CPA_COMMIT();
            }
            {
                int ko = c*16;
                wmma::fragment<wmma::matrix_a,16,16,16,bf16,wmma::row_major> ah[2], al[2];
                #pragma unroll
                for (int i = 0; i < 2; i++) {
                    wmma::load_matrix_sync(ah[i], sZh + (i*16)*ZLD + ko, ZLD);
                    wmma::load_matrix_sync(al[i], sZl + (i*16)*ZLD + ko, ZLD);
                }
                wmma::fragment<wmma::matrix_b,16,16,16,bf16,wmma::row_major> bh[2], bl[2];
                #pragma unroll
                for (int j = 0; j < 2; j++) {
                    wmma::load_matrix_sync(bh[j], curH + w*32 + j*16, WLD);
                    wmma::load_matrix_sync(bl[j], curL + w*32 + j*16, WLD);
                }
                #pragma unroll
                for (int i = 0; i < 2; i++)
                    #pragma unroll
                    for (int j = 0; j < 2; j++) {
                        wmma::mma_sync(acc1[i][j], ah[i], bh[j], acc1[i][j]);
                        wmma::mma_sync(acc1[i][j], ah[i], bl[j], acc1[i][j]);
                        wmma::mma_sync(acc1[i][j], al[i], bh[j], acc1[i][j]);
                    }
            }
            if (c < 7) CPA_WAIT0();
            __syncthreads();
        }

        // ---- Phase C: hidden epilogue (bias+relu+split), 2 N-halves via scrF ----
        #pragma unroll
        for (int r = 0; r < 2; r++) {
            if (r) __syncthreads();
            if ((w >> 2) == r) {
                #pragma unroll
                for (int i = 0; i < 2; i++)
                    #pragma unroll
                    for (int j = 0; j < 2; j++)
                        wmma::store_matrix_sync(scrF + (i*16)*132 + (w & 3)*32 + j*16,
                                                acc1[i][j], 132, wmma::mem_row_major);
            }
            __syncthreads();
            #pragma unroll 4
            for (int it = 0; it < 16; it++) {
                int idx = t + it*256;
                int rr = idx >> 7, c = idx & 127;
                int C = r*128 + c;
                float v = fmaxf(scrF[rr*132 + c] + __ldg(b1 + C), 0.0f);
                bf16 hi, lo; bsplit(v, hi, lo);
                sHh[rr*WLD + C] = hi;
                sHl[rr*WLD + C] = lo;
            }
        }
    }
    __syncthreads();

    // ---- Phase D: gemm2  out[32x128] = hidden[32x256] @ W2[256x128], 16 chunks of 16 ----
    {
        int wm = w & 1, wn = w >> 1;             // 2 x 4 warps, warp tile 16x32
        wmma::fragment<wmma::accumulator,16,16,16,float> acc2[2];
        #pragma unroll
        for (int j = 0; j < 2; j++) wmma::fill_fragment(acc2[j], 0.0f);

        {
            #pragma unroll
            for (int i = 0; i < 2; i++) {
                int idx = t + i*256;             // 0..511: hi 256 uint4, lo 256
                int m = idx >> 8, j = idx & 255;
                int r = j >> 4, p = j & 15;
                const bf16* src = (m ? W2l : W2h) + (size_t)r*128 + p*8;
                bf16* dst = w2base + m*(16*W2LD) + r*W2LD + p*8;
                cpa16(dst, src);
            }
            CPA_COMMIT();
        }
        CPA_WAIT0();
        __syncthreads();

        #pragma unroll
        for (int c2 = 0; c2 < 16; c2++) {
            const bf16* cH = w2base + (c2&1)*4352;
            const bf16* cL = cH + 16*W2LD;
            if (c2 < 15) {
                bf16* nb = w2base + ((c2+1)&1)*4352;
                #pragma unroll
                for (int i = 0; i < 2; i++) {
                    int idx = t + i*256;
                    int m = idx >> 8, j = idx & 255;
                    int r = j >> 4, p = j & 15;
                    const bf16* src = (m ? W2l : W2h) + (size_t)((c2+1)*16 + r)*128 + p*8;
                    bf16* dst = nb + m*(16*W2LD) + r*W2LD + p*8;
                    cpa16(dst, src);
                }
                CPA_COMMIT();
            }
            {
                int ko = c2*16;
                wmma::fragment<wmma::matrix_a,16,16,16,bf16,wmma::row_major> ah, al;
                wmma::load_matrix_sync(ah, sHh + (wm*16)*WLD + ko, WLD);
                wmma::load_matrix_sync(al, sHl + (wm*16)*WLD + ko, WLD);
                wmma::fragment<wmma::matrix_b,16,16,16,bf16,wmma::row_major> bh0, bh1, bl0, bl1;
                int nb2 = wn*32;
                wmma::load_matrix_sync(bh0, cH + nb2,      W2LD);
                wmma::load_matrix_sync(bh1, cH + nb2 + 16, W2LD);
                wmma::load_matrix_sync(bl0, cL + nb2,      W2LD);
                wmma::load_matrix_sync(bl1, cL + nb2 + 16, W2LD);
                wmma::mma_sync(acc2[0], ah, bh0, acc2[0]);
                wmma::mma_sync(acc2[1], ah, bh1, acc2[1]);
                wmma::mma_sync(acc2[0], ah, bl0, acc2[0]);
                wmma::mma_sync(acc2[1], ah, bl1, acc2[1]);
                wmma::mma_sync(acc2[0], al, bh0, acc2[0]);
                wmma::mma_sync(acc2[1], al, bh1, acc2[1]);
            }
            if (c2 < 15) CPA_WAIT0();
            __syncthreads();
        }
        #pragma unroll
        for (int j = 0; j < 2; j++)
            wmma::store_matrix_sync(scrF + (wm*16)*132 + wn*32 + j*16, acc2[j],
                                    132, wmma::mem_row_major);
        __syncthreads();
    }

    // ---- Phase E: final epilogue (bias + BN [+relu]) -> g_h (layers 0,1) or smem split (layer 2) ----
    const float BNS = 0.99999500003749971f;    // 1/sqrt(1+1e-5)
    {
        int ccol = t & 127;
        float rsum = 0.0f;
        #pragma unroll 4
        for (int it = 0; it < 16; it++) {
            int idx = t + it*256;
            int r = idx >> 7;                      // 0..31
            float v = scrF[r*132 + ccol] + __ldg(b2 + ccol);
            v = v*(BNS*__ldg(gamma + ccol)) + __ldg(beta + ccol);
            if (!last) {
                v = fmaxf(v, 0.0f);
                g_h[(size_t)(m0 + r)*128 + ccol] = v;
            } else {
                bf16 hi, lo; bsplit(v, hi, lo);
                sZh[r*ZLD + ccol] = hi;            // act split -> z region (hidden dead)
                sZl[r*ZLD + ccol] = lo;
                rsum += v;
            }
        }
        if (last)
            atomicAdd(&g_res[(m0 >> 9)*128 + ccol], rsum);
    }

    if (!last) {
        __threadfence();
        __syncthreads();
        if (t == 0) atomicAdd(&g_done[l*BB + g], 1);
        return;
    }

    // ---- Phase F: fused partitioner  cl[32x128] = act[32x128] @ pW1[128x128], S -> smem ----
    {
        int wm = w & 1, wn = w >> 1;             // 2 x 4 warps, warp tile 16x32
        wmma::fragment<wmma::accumulator,16,16,16,float> acc3[2];
        #pragma unroll
        for (int i = 0; i < 2; i++) wmma::fill_fragment(acc3[i], 0.0f);

        #pragma unroll
        for (int c = 0; c < 4; c++) {
            __syncthreads();
            #pragma unroll
            for (int i = 0; i < 4; i++) {        // 1024 uint4: hi 512, lo 512
                int idx = t + i*256;
                int m = idx >> 9, j = idx & 511;
                int r = j >> 4, p = j & 15;
                const bf16* src = (m ? Pl : Ph) + (size_t)(c*32 + r)*128 + p*8;
                bf16* dst = (m ? sPl : sPh) + r*W2LD + p*8;
                *(uint4*)dst = *(const uint4*)src;
            }
            __syncthreads();
            #pragma unroll
            for (int kb = 0; kb < 2; kb++) {
                wmma::fragment<wmma::matrix_a,16,16,16,bf16,wmma::row_major> ah, al;
                wmma::load_matrix_sync(ah, sZh + (wm*16)*ZLD + c*32 + kb*16, ZLD);
                wmma::load_matrix_sync(al, sZl + (wm*16)*ZLD + c*32 + kb*16, ZLD);
                wmma::fragment<wmma::matrix_b,16,16,16,bf16,wmma::row_major> bh0, bh1, bl0, bl1;
                int nb2 = wn*32;
                wmma::load_matrix_sync(bh0, sPh + (kb*16)*W2LD + nb2,      W2LD);
                wmma::load_matrix_sync(bh1, sPh + (kb*16)*W2LD + nb2 + 16, W2LD);
                wmma::load_matrix_sync(bl0, sPl + (kb*16)*W2LD + nb2,      W2LD);
                wmma::load_matrix_sync(bl1, sPl + (kb*16)*W2LD + nb2 + 16, W2LD);
                wmma::mma_sync(acc3[0], ah, bh0, acc3[0]);
                wmma::mma_sync(acc3[1], ah, bh1, acc3[1]);
                wmma::mma_sync(acc3[0], ah, bl0, acc3[0]);
                wmma::mma_sync(acc3[1], ah, bl1, acc3[1]);
                wmma::mma_sync(acc3[0], al, bh0, acc3[0]);
                wmma::mma_sync(acc3[1], al, bh1, acc3[1]);
            }
        }
        __syncthreads();
        #pragma unroll
        for (int j = 0; j < 2; j++)
            wmma::store_matrix_sync(scrFp + ((w & 1)*16)*132 + (w >> 1)*32 + j*16, acc3[j],
                                    132, wmma::mem_row_major);
        if (t < 255) w2s[t] = (t < 250) ? pW2[t] : pb2[t - 250];
        __syncthreads();

        if (t < 32) {
            float cr[50];
            #pragma unroll
            for (int j = 0; j < 50; j++)
                cr[j] = fmaxf(scrFp[t*132 + j] + pbias[j], 0.0f);
            float l2[5];
            #pragma unroll
            for (int k = 0; k < 5; k++) {
                float a = w2s[250 + k];
                #pragma unroll
                for (int j = 0; j < 50; j++) a += cr[j]*w2s[j*5 + k];
                l2[k] = a;
            }
            float m = l2[0];
            #pragma unroll
            for (int k = 1; k < 5; k++) m = fmaxf(m, l2[k]);
            float e[5], s = 0.0f;
            #pragma unroll
            for (int k = 0; k < 5; k++) { e[k] = expf(l2[k] - m); s += e[k]; }
            float inv = 1.0f/s;
            #pragma unroll
            for (int k = 0; k < 5; k++) sScf[t*5 + k] = e[k]*inv;
        }
    }
    __syncthreads();

    // ---- Phase G: cf partial accumulate (S^T h for own 32 nodes) ----
    {
        int c = t & 127, half = t >> 7;
        float acc[5] = {0,0,0,0,0};
        #pragma unroll 4
        for (int n = half*16; n < half*16 + 16; n++) {
            float hv = __bfloat162float(sZh[n*ZLD + c]) + __bfloat162float(sZl[n*ZLD + c]);
            #pragma unroll
            for (int k = 0; k < 5; k++) acc[k] += sScf[n*5 + k]*hv;
        }
        #pragma unroll
        for (int k = 0; k < 5; k++)
            atomicAdd(&g_cfnum[((size_t)g*5 + k)*128 + c], acc[k]);
        if (t < 5) {
            float s = 0.0f;
            #pragma unroll
            for (int n = 0; n < 32; n++) s += sScf[n*5 + t];
            atomicAdd(&g_ssum[g*5 + t], s);
        }
    }
}

// ---------------- finale: cf divide + VQ + attention/gate/classifier, one block per graph ----------------
__global__ void finale_kernel(const float* __restrict__ codebook,
                              const float* __restrict__ Wq, const float* __restrict__ Wk,
                              const float* __restrict__ Wv, const float* __restrict__ Wo,
                              const float* __restrict__ gW1, const float* __restrict__ gb1,
                              const float* __restrict__ gW2, const float* __restrict__ gb2,
                              const float* __restrict__ cW1, const float* __restrict__ cb1,
                              const float* __restrict__ cW2, const float* __restrict__ cb2,
                              const float* __restrict__ cW3, const float* __restrict__ cb3,
                              float* __restrict__ out)
{
    __shared__ __align__(16) float sh[2816];         // tail scratch
    __shared__ __align__(16) float cfv[5*128];
    __shared__ float zq5[5*128];
    __shared__ float wbest[5][4];
    __shared__ int   widx[5][4];
    __shared__ int   bidx[5];

    int g = blockIdx.x, t = threadIdx.x;             // 640 threads
    int k = t >> 7, c = t & 127;

    // ---- cf: divide ----
    cfv[k*128 + c] = g_cfnum[((size_t)g*5 + k)*128 + c] / (g_ssum[g*5 + k] + 1e-6f);
    __syncthreads();

    // ---- VQ: nearest codebook row per cluster (5 rows x 4 warps each) ----
    {
        int w4 = c >> 5, lane = c & 31;
        float4 fv = ((const float4*)(cfv + k*128))[lane];
        float best = 3.4e38f;
        int bi = 0;
        for (int rr = w4; rr < CBN; rr += 4) {
            const float4* cb4 = (const float4*)(codebook + (size_t)rr*128);
            float4 cv = cb4[lane];
            float dx = cv.x - fv.x, dy = cv.y - fv.y, dz = cv.z - fv.z, dw = cv.w - fv.w;
            float d = dx*dx + dy*dy + dz*dz + dw*dw;
            #pragma unroll
            for (int o = 16; o; o >>= 1) d += __shfl_xor_sync(0xffffffff, d, o);
            if (d < best) { best = d; bi = rr; }
        }
        if (lane == 0) { wbest[k][w4] = best; widx[k][w4] = bi; }
        __syncthreads();
        if (t < 5) {
            float bb = wbest[t][0]; int ii = widx[t][0];
            for (int j = 1; j < 4; j++)
                if (wbest[t][j] < bb || (wbest[t][j] == bb && widx[t][j] < ii)) { bb = wbest[t][j]; ii = widx[t][j]; }
            bidx[t] = ii;
        }
        __syncthreads();
        zq5[k*128 + c] = codebook[(size_t)bidx[k]*128 + c];
    }
    __syncthreads();

    // ---- tail: attention + gate + classifier ----
    float* r    = sh;            // 128
    float* qv   = sh + 128;      // 128
    float* kk   = sh + 256;      // 640
    float* vv   = sh + 896;      // 640
    float* sc   = sh + 1536;     // 20
    float* aw   = sh + 1568;     // 20
    float* attv = sh + 1600;     // 128
    float* attn = sh + 1728;     // 128
    float* g1   = sh + 1856;     // 64
    float* fus  = sh + 1920;     // 128
    float* z1   = sh + 2048;     // 512
    float* z2   = sh + 2560;     // 256

    if (t < 128) r[t] = g_res[g*128 + t]*(1.0f/NPGC);
    __syncthreads();

    if (t < 128) {
        float a = 0.0f;
        for (int k2 = 0; k2 < 128; k2++) a += r[k2]*Wq[k2*128 + t];
        qv[t] = a;
    }
    {
        float a = 0.0f;
        const float* zrow = zq5 + k*128;
        for (int k2 = 0; k2 < 128; k2++) a += zrow[k2]*Wk[k2*128 + c];
        kk[t] = a;
        float b = 0.0f;
        for (int k2 = 0; k2 < 128; k2++) b += zrow[k2]*Wv[k2*128 + c];
        vv[t] = b;
    }
    __syncthreads();

    if (t < 20) {
        int hh = t/5, j = t%5;
        float s = 0.0f;
        for (int d2 = 0; d2 < 32; d2++) s += qv[hh*32 + d2]*kk[j*128 + hh*32 + d2];
        sc[t] = s*0.17677669529663687f;              // 1/sqrt(32)
    }
    __syncthreads();
    if (t < 4) {
        float m = -1e30f;
        #pragma unroll
        for (int j = 0; j < 5; j++) m = fmaxf(m, sc[t*5 + j]);
        float e[5], s = 0.0f;
        #pragma unroll
        for (int j = 0; j < 5; j++) { e[j] = expf(sc[t*5 + j] - m); s += e[j]; }
        float inv = 1.0f/s;
        #pragma unroll
        for (int j = 0; j < 5; j++) aw[t*5 + j] = e[j]*inv;
    }
    __syncthreads();
    if (t < 128) {
        int hh = t >> 5;
        float a = 0.0f;
        #pragma unroll
        for (int j = 0; j < 5; j++) a += aw[hh*5 + j]*vv[j*128 + t];
        attv[t] = a;
    }
    __syncthreads();
    if (t < 128) {
        float a = 0.0f;
        for (int k2 = 0; k2 < 128; k2++) a += attv[k2]*Wo[k2*128 + t];
        attn[t] = a;
    }
    __syncthreads();
    if (t < 64) {
        float a = gb1[t];
        for (int k2 = 0; k2 < 128; k2++) a += r[k2]*gW1[k2*64 + t];
        for (int k2 = 0; k2 < 128; k2++) a += attn[k2]*gW1[(128 + k2)*64 + t];
        g1[t] = fmaxf(a, 0.0f);
    }
    __syncthreads();
    if (t < 128) {
        float a = gb2[t];
        for (int k2 = 0; k2 < 64; k2++) a += g1[k2]*gW2[k2*128 + t];
        float gg = 1.0f/(1.0f + expf(-a));
        fus[t] = gg*r[t] + (1.0f - gg)*attn[t];
    }
    __syncthreads();
    if (t < 512) {
        float a = cb1[t];
        for (int k2 = 0; k2 < 128; k2++) a += fus[k2]*cW1[k2*512 + t];
        z1[t] = fmaxf(a, 0.0f);
    }
    __syncthreads();
    if (t < 256) {
        float a = cb2[t];
        for (int k2 = 0; k2 < 512; k2++) a += z1[k2]*cW2[k2*256 + t];
        z2[t] = fmaxf(a, 0.0f);
    }
    __syncthreads();
    if (t < 2) {
        float a = cb3[t];
        for (int k2 = 0; k2 < 256; k2++) a += z2[k2]*cW3[k2*2 + t];
        out[g*2 + t] = a;
    }
}

// ---------------- host launch ----------------
extern "C" void kernel_launch(void* const* d_in, const int* in_sizes, int n_in,
                              void* d_out, int out_size) {
    (void)in_sizes; (void)n_in; (void)out_size;
    const int*   x     = (const int*)d_in[0];
    const int*   ei    = (const int*)d_in[1];
    const float* emb   = (const float*)d_in[3];
    const float* gW1   = (const float*)d_in[4];
    const float* gb1v  = (const float*)d_in[5];
    const float* gW2   = (const float*)d_in[6];
    const float* gb2v  = (const float*)d_in[7];
    const float* bng   = (const float*)d_in[8];
    const float* bnb   = (const float*)d_in[9];
    const float* pW1   = (const float*)d_in[10];
    const float* pb1   = (const float*)d_in[11];
    const float* pW2   = (const float*)d_in[12];
    const float* pb2   = (const float*)d_in[13];
    const float* Wq    = (const float*)d_in[14];
    const float* Wk    = (const float*)d_in[15];
    const float* Wv    = (const float*)d_in[16];
    const float* Wo    = (const float*)d_in[17];
    const float* gateW1= (const float*)d_in[18];
    const float* gateb1= (const float*)d_in[19];
    const float* gateW2= (const float*)d_in[20];
    const float* gateb2= (const float*)d_in[21];
    const float* cbk   = (const float*)d_in[22];
    const float* cW1   = (const float*)d_in[23];
    const float* cb1   = (const float*)d_in[24];
    const float* cW2   = (const float*)d_in[25];
    const float* cb2   = (const float*)d_in[26];
    const float* cW3   = (const float*)d_in[27];
    const float* cb3   = (const float*)d_in[28];
    float* out = (float*)d_out;

    bf16 *w1hi, *w1lo, *w2hi, *w2lo, *pwhi, *pwlo;
    float *ppb1;
    cudaGetSymbolAddress((void**)&w1hi, g_w1hi);
    cudaGetSymbolAddress((void**)&w1lo, g_w1lo);
    cudaGetSymbolAddress((void**)&w2hi, g_w2hi);
    cudaGetSymbolAddress((void**)&w2lo, g_w2lo);
    cudaGetSymbolAddress((void**)&pwhi, g_pwhi);
    cudaGetSymbolAddress((void**)&pwlo, g_pwlo);
    cudaGetSymbolAddress((void**)&ppb1, g_pb1);

    cudaFuncSetAttribute(ginlayer, cudaFuncAttributeMaxDynamicSharedMemorySize, GIN_SMEM);

    setup_kernel<<<64 + 256, 512>>>(ei, gW1, gW2, pW1, pb1);

    ginlayer<<<3*(NN/32), 256, GIN_SMEM>>>(
        w1hi, w1lo, w2hi, w2lo,
        gb1v, gb2v, bng, bnb,
        pwhi, pwlo, ppb1, pW2, pb2, x, emb);

    finale_kernel<<<BB, 640>>>(cbk, Wq, Wk, Wv, Wo, gateW1, gateb1, gateW2, gateb2,
                               cW1, cb1, cW2, cb2, cW3, cb3, out);
}